// round 9
// baseline (speedup 1.0000x reference)
#include <cuda_runtime.h>
#include <cuda_bf16.h>
#include <cuda_fp16.h>
#include <math.h>
#include <stdint.h>

#define D_MODEL   256
#define D_INNER   512
#define CONV_CH   640
#define D_IN_PROJ 1160
#define NPAD1     1280
#define SEQ       64
#define NSEQ      512
#define NTOK      32768
#define KFIN      1024

// ---------------- scratch ------------------------------------------------------
__device__ float  g_Zh  [(size_t)NTOK * NPAD1];
__device__ float  g_Zv  [(size_t)NTOK * NPAD1];
__device__ __half g_Xhi [(size_t)NTOK * D_MODEL];
__device__ __half g_Xlo [(size_t)NTOK * D_MODEL];
__device__ __half g_Whhi[(size_t)NPAD1 * D_MODEL];
__device__ __half g_Whlo[(size_t)NPAD1 * D_MODEL];
__device__ __half g_Wvhi[(size_t)NPAD1 * D_MODEL];
__device__ __half g_Wvlo[(size_t)NPAD1 * D_MODEL];
__device__ __half g_Y   [(size_t)NTOK * KFIN];
__device__ __half g_WcBhi[(size_t)D_MODEL * KFIN];
__device__ __half g_WcBlo[(size_t)D_MODEL * KFIN];

// ---------------- helpers ------------------------------------------------------
__device__ __forceinline__ uint32_t smem_u32(const void* p) {
    uint32_t a;
    asm("{ .reg .u64 t; cvta.to.shared.u64 t, %1; cvt.u32.u64 %0, t; }" : "=r"(a) : "l"(p));
    return a;
}
__device__ __forceinline__ uint32_t sw64(uint32_t off) {   // 64B-row swizzle
    return off ^ ((off >> 3) & 0x30);
}
#define CP16(dst, src) \
    asm volatile("cp.async.cg.shared.global [%0], [%1], 16;" :: "r"(dst), "l"(src))
#define CP_COMMIT() asm volatile("cp.async.commit_group;" ::: "memory")
#define CP_WAIT(n)  asm volatile("cp.async.wait_group %0;" :: "n"(n) : "memory")

typedef unsigned long long ull;
__device__ __forceinline__ ull pack2(float lo, float hi) {
    ull r; asm("mov.b64 %0, {%1, %2};" : "=l"(r) : "f"(lo), "f"(hi)); return r;
}
#define FMA_X2(d, a, b, c) \
    asm("fma.rn.f32x2 %0, %1, %2, %3;" : "=l"(d) : "l"(a), "l"(b), "l"(c))
#define MUL_X2(d, a, b) \
    asm("mul.rn.f32x2 %0, %1, %2;" : "=l"(d) : "l"(a), "l"(b))

// ---------------- conversion kernels -------------------------------------------
__global__ void cvt_x_kernel(const float* __restrict__ in) {
    size_t i = (size_t)blockIdx.x * 256 + threadIdx.x;
    float4 v = ((const float4*)in)[i];
    __half h0 = __float2half(v.x), h1 = __float2half(v.y);
    __half h2 = __float2half(v.z), h3 = __float2half(v.w);
    __half2 hi01 = __halves2half2(h0, h1), hi23 = __halves2half2(h2, h3);
    __half2 lo01 = __halves2half2(__float2half(v.x - __half2float(h0)),
                                  __float2half(v.y - __half2float(h1)));
    __half2 lo23 = __halves2half2(__float2half(v.z - __half2float(h2)),
                                  __float2half(v.w - __half2float(h3)));
    ((__half2*)g_Xhi)[2 * i]     = hi01;
    ((__half2*)g_Xhi)[2 * i + 1] = hi23;
    ((__half2*)g_Xlo)[2 * i]     = lo01;
    ((__half2*)g_Xlo)[2 * i + 1] = lo23;
}

__global__ void prep_w_kernel(const float* __restrict__ wh, const float* __restrict__ wv) {
    int i = blockIdx.x * 256 + threadIdx.x;
    const float* w = blockIdx.y ? wv : wh;
    __half* whi = blockIdx.y ? g_Wvhi : g_Whhi;
    __half* wlo = blockIdx.y ? g_Wvlo : g_Whlo;
    if (i < NPAD1 * D_MODEL) {
        int n = i >> 8;
        float v = (n < D_IN_PROJ) ? w[i] : 0.f;
        __half h = __float2half(v);
        whi[i] = h;
        wlo[i] = __float2half(v - __half2float(h));
    }
}

// ---------------- mma.sync split-fp16 GEMM --------------------------------------
// C = A*Bhi + A*Blo (+ Alo*Bhi on the dt-containing N-tile).
#define BMg 128
#define BNg 128
#define TILE_Bg  8192
#define STAGE_Bg 32768
#define GSMEM    (3 * STAGE_Bg)

__global__ void __launch_bounds__(256, 2) gemm_mma(
    const __half* __restrict__ A, const __half* __restrict__ Alo,
    const __half* __restrict__ B0hi, const __half* __restrict__ B0lo,
    const __half* __restrict__ B1hi, const __half* __restrict__ B1lo,
    float* __restrict__ C0, float* __restrict__ C1,
    int K, int ldc, const float* __restrict__ bias, int dtn)
{
    extern __shared__ __half sm[];
    const uint32_t smb = smem_u32(sm);
    const int tid = threadIdx.x, lane = tid & 31, wid = tid >> 5;
    const int m0 = blockIdx.x * BMg, n0 = blockIdx.y * BNg;
    const int wm = (wid & 1) * 64, wn = 32 * (wid >> 1);
    const int nk = K >> 5;
    const bool need3 = (n0 == dtn);

    const __half* Bhi = blockIdx.z ? B1hi : B0hi;
    const __half* Blo = blockIdx.z ? B1lo : B0lo;
    float* C = blockIdx.z ? C1 : C0;

    uint32_t arow[4], brow[2];
#pragma unroll
    for (int mt = 0; mt < 4; mt++)
        arow[mt] = (uint32_t)(wm + mt * 16 + (lane & 15)) * 64 + (lane >> 4) * 16;
#pragma unroll
    for (int nb = 0; nb < 2; nb++)
        brow[nb] = (uint32_t)(wn + nb * 16 + (lane & 15)) * 64 + (lane >> 4) * 16;

    float acc[4][4][4];
#pragma unroll
    for (int a = 0; a < 4; a++)
#pragma unroll
        for (int b = 0; b < 4; b++)
#pragma unroll
            for (int c = 0; c < 4; c++) acc[a][b][c] = 0.f;

    const int lrow = tid & 127, hf = tid >> 7;
    const uint32_t rb = (uint32_t)lrow * 64 + hf * 32;

    auto load_stage = [&](int s, int c) {
        const int koff = c * 32 + hf * 16;
        const uint32_t base = smb + s * STAGE_Bg;
        const __half* pA   = A   + (size_t)(m0 + lrow) * K + koff;
        const __half* pBhi = Bhi + (size_t)(n0 + lrow) * K + koff;
        const __half* pBlo = Blo + (size_t)(n0 + lrow) * K + koff;
#pragma unroll
        for (int ch = 0; ch < 2; ch++) {
            uint32_t d = sw64(rb + ch * 16);
            CP16(base + d, pA + ch * 8);
            CP16(base + 2 * TILE_Bg + d, pBhi + ch * 8);
            CP16(base + 3 * TILE_Bg + d, pBlo + ch * 8);
        }
        if (need3) {
            const __half* pAlo = Alo + (size_t)(m0 + lrow) * K + koff;
#pragma unroll
            for (int ch = 0; ch < 2; ch++)
                CP16(base + TILE_Bg + sw64(rb + ch * 16), pAlo + ch * 8);
        }
        CP_COMMIT();
    };

    load_stage(0, 0);
    load_stage(1, 1);

    for (int c = 0; c < nk; c++) {
        if (c + 1 < nk) CP_WAIT(1); else CP_WAIT(0);
        __syncthreads();
        if (c + 2 < nk) load_stage((c + 2) % 3, c + 2);

        const uint32_t base = smb + (c % 3) * STAGE_Bg;
        const uint32_t aB = base, aLoB = base + TILE_Bg;
        const uint32_t bHiB = base + 2 * TILE_Bg, bLoB = base + 3 * TILE_Bg;
#pragma unroll
        for (int ks = 0; ks < 2; ks++) {
            uint32_t af[4][4], alo[4][4], bhi[2][4], blo[2][4];
#pragma unroll
            for (int mt = 0; mt < 4; mt++) {
                uint32_t sw = sw64(arow[mt] + ks * 32);
                asm volatile("ldmatrix.sync.aligned.m8n8.x4.shared.b16 {%0,%1,%2,%3}, [%4];"
                             : "=r"(af[mt][0]), "=r"(af[mt][1]), "=r"(af[mt][2]), "=r"(af[mt][3])
                             : "r"(aB + sw));
            }
#pragma unroll
            for (int nb = 0; nb < 2; nb++) {
                uint32_t sw = sw64(brow[nb] + ks * 32);
                asm volatile("ldmatrix.sync.aligned.m8n8.x4.shared.b16 {%0,%1,%2,%3}, [%4];"
                             : "=r"(bhi[nb][0]), "=r"(bhi[nb][1]), "=r"(bhi[nb][2]), "=r"(bhi[nb][3])
                             : "r"(bHiB + sw));
                asm volatile("ldmatrix.sync.aligned.m8n8.x4.shared.b16 {%0,%1,%2,%3}, [%4];"
                             : "=r"(blo[nb][0]), "=r"(blo[nb][1]), "=r"(blo[nb][2]), "=r"(blo[nb][3])
                             : "r"(bLoB + sw));
            }
#define MMA_PASS(AF, BF)                                                              \
            _Pragma("unroll")                                                         \
            for (int mt = 0; mt < 4; mt++)                                            \
                _Pragma("unroll")                                                     \
                for (int nb = 0; nb < 2; nb++) {                                      \
                    asm volatile(                                                     \
                        "mma.sync.aligned.m16n8k16.row.col.f32.f16.f16.f32 "          \
                        "{%0,%1,%2,%3}, {%4,%5,%6,%7}, {%8,%9}, {%0,%1,%2,%3};"       \
                        : "+f"(acc[mt][nb * 2][0]), "+f"(acc[mt][nb * 2][1]),         \
                          "+f"(acc[mt][nb * 2][2]), "+f"(acc[mt][nb * 2][3])          \
                        : "r"(AF[mt][0]), "r"(AF[mt][1]), "r"(AF[mt][2]), "r"(AF[mt][3]), \
                          "r"(BF[nb][0]), "r"(BF[nb][2]));                            \
                    asm volatile(                                                     \
                        "mma.sync.aligned.m16n8k16.row.col.f32.f16.f16.f32 "          \
                        "{%0,%1,%2,%3}, {%4,%5,%6,%7}, {%8,%9}, {%0,%1,%2,%3};"       \
                        : "+f"(acc[mt][nb * 2 + 1][0]), "+f"(acc[mt][nb * 2 + 1][1]), \
                          "+f"(acc[mt][nb * 2 + 1][2]), "+f"(acc[mt][nb * 2 + 1][3])  \
                        : "r"(AF[mt][0]), "r"(AF[mt][1]), "r"(AF[mt][2]), "r"(AF[mt][3]), \
                          "r"(BF[nb][1]), "r"(BF[nb][3]));                            \
                }
            MMA_PASS(af, bhi)
            MMA_PASS(af, blo)
            if (need3) {
#pragma unroll
                for (int mt = 0; mt < 4; mt++) {
                    uint32_t sw = sw64(arow[mt] + ks * 32);
                    asm volatile("ldmatrix.sync.aligned.m8n8.x4.shared.b16 {%0,%1,%2,%3}, [%4];"
                                 : "=r"(alo[mt][0]), "=r"(alo[mt][1]), "=r"(alo[mt][2]), "=r"(alo[mt][3])
                                 : "r"(aLoB + sw));
                }
                MMA_PASS(alo, bhi)
            }
#undef MMA_PASS
        }
    }

#pragma unroll
    for (int mt = 0; mt < 4; mt++) {
        int row = m0 + wm + mt * 16 + (lane >> 2);
#pragma unroll
        for (int nt = 0; nt < 4; nt++) {
            int col = n0 + wn + nt * 8 + (lane & 3) * 2;
            float2 v0 = make_float2(acc[mt][nt][0], acc[mt][nt][1]);
            float2 v1 = make_float2(acc[mt][nt][2], acc[mt][nt][3]);
            if (bias) {
                float b0 = bias[col], b1 = bias[col + 1];
                v0.x += b0; v0.y += b1; v1.x += b0; v1.y += b1;
            }
            *(float2*)&C[(size_t)row * ldc + col] = v0;
            *(float2*)&C[(size_t)(row + 8) * ldc + col] = v1;
        }
    }
}

// ---------------- fused conv + SiLU + softplus + SSM scan + gate + RMSnorm ------
// 1024 threads: chan = tid&511 (head*64+p), nh = tid>>9 picks state half.
// Each thread holds 32 of 64 states (h2[16]); y combined via smem.
__global__ void __launch_bounds__(1024, 1) scan_kernel(
    const float* __restrict__ cwh, const float* __restrict__ cbh,
    const float* __restrict__ dtbh, const float* __restrict__ Alh,
    const float* __restrict__ Dh_, const float* __restrict__ nwh,
    const float* __restrict__ cwv, const float* __restrict__ cbv,
    const float* __restrict__ dtbv, const float* __restrict__ Alv,
    const float* __restrict__ Dv_, const float* __restrict__ nwv)
{
    const int tid  = threadIdx.x;
    const int chan = tid & 511;
    const int nh   = tid >> 9;
    const int head = chan >> 6;
    const int dir  = blockIdx.x >> 9;
    const int s    = blockIdx.x & 511;

    const float* Z       = dir ? g_Zv : g_Zh;
    const float* conv_w  = dir ? cwv : cwh;
    const float* conv_b  = dir ? cbv : cbh;
    const float* dt_bias = dir ? dtbv : dtbh;
    const float* A_log   = dir ? Alv : Alh;
    const float* Dvv     = dir ? Dv_ : Dh_;
    const float* norm_w  = dir ? nwv : nwh;
    const int ycol_off   = dir ? 0 : 512;

    int base, stride;
    if (dir) { int b = s >> 6, w = s & 63; base = b * 4096 + w; stride = 64; }
    else     { base = s * 64; stride = 1; }

    __shared__ __align__(16) float ring[8][CONV_CH];
    __shared__ __align__(16) float zbuf[4][512];
    __shared__ __align__(16) float dtbuf[4][8];
    __shared__ __align__(16) float Bsh[64];
    __shared__ __align__(16) float Csh[64];
    __shared__ __align__(16) float ypar[512];
    __shared__ float dt_s[8], dA_s[8], Aneg_s[8], dtb_s[8];
    __shared__ float red[16];

    for (int i = tid; i < 8 * CONV_CH; i += 1024) (&ring[0][0])[i] = 0.f;
    if (tid < 8) { Aneg_s[tid] = -expf(A_log[tid]); dtb_s[tid] = dt_bias[tid]; }

    const float w0 = conv_w[chan * 4 + 0], w1 = conv_w[chan * 4 + 1];
    const float w2 = conv_w[chan * 4 + 2], w3 = conv_w[chan * 4 + 3];
    const float cb = conv_b[chan];
    float u0 = 0.f, u1 = 0.f, u2 = 0.f, u3 = 0.f, cb2 = 0.f;
    const int c2 = 512 + chan;
    const bool bcduty = (nh == 1) && (chan < 128);
    if (bcduty) {
        u0 = conv_w[c2 * 4 + 0]; u1 = conv_w[c2 * 4 + 1];
        u2 = conv_w[c2 * 4 + 2]; u3 = conv_w[c2 * 4 + 3];
        cb2 = conv_b[c2];
    }
    const float Dhv = Dvv[head];
    const float nw = norm_w[chan];

    ull h2[16];
#pragma unroll
    for (int n = 0; n < 16; n++) h2[n] = pack2(0.f, 0.f);

    const uint32_t ring_b = smem_u32(&ring[0][0]);
    const uint32_t zbuf_b = smem_u32(&zbuf[0][0]);
    const uint32_t dtb_b  = smem_u32(&dtbuf[0][0]);

    auto prefetch = [&](int tt) {
        if (tt < SEQ) {
            const float* row = Z + (size_t)(base + tt * stride) * NPAD1;
            if (tid < 160)       CP16(ring_b + (tt & 7) * (CONV_CH * 4) + tid * 16, row + 512 + tid * 4);
            else if (tid < 288)  CP16(zbuf_b + (tt & 3) * 2048 + (tid - 160) * 16, row + (tid - 160) * 4);
            else if (tid < 290)  CP16(dtb_b + (tt & 3) * 32 + (tid - 288) * 16, row + 1152 + (tid - 288) * 4);
        }
        CP_COMMIT();
    };

    __syncthreads();
    prefetch(0);
    prefetch(1);

    for (int t = 0; t < SEQ; t++) {
        if (t < SEQ - 1) CP_WAIT(1); else CP_WAIT(0);
        __syncthreads();
        prefetch(t + 2);

        const int slot = t & 7;
        if (tid < 8) {
            float draw = dtbuf[t & 3][tid] + dtb_s[tid];
            float dt = (draw > 20.f) ? draw : log1pf(expf(draw));
            dt_s[tid] = dt;
            dA_s[tid] = expf(dt * Aneg_s[tid]);
        }

        const int s0 = (t + 5) & 7, s1 = (t + 6) & 7, s2 = (t + 7) & 7, s3 = slot;
        float xv = cb;
        xv = fmaf(ring[s0][chan], w0, xv);
        xv = fmaf(ring[s1][chan], w1, xv);
        xv = fmaf(ring[s2][chan], w2, xv);
        xv = fmaf(ring[s3][chan], w3, xv);
        xv = xv / (1.f + expf(-xv));
        if (bcduty) {
            float v = cb2;
            v = fmaf(ring[s0][c2], u0, v);
            v = fmaf(ring[s1][c2], u1, v);
            v = fmaf(ring[s2][c2], u2, v);
            v = fmaf(ring[s3][c2], u3, v);
            v = v / (1.f + expf(-v));
            if (chan < 64) Bsh[chan] = v; else Csh[chan - 64] = v;
        }
        __syncthreads();

        const float dA  = dA_s[head];
        const float dtx = dt_s[head] * xv;
        const ull dA2  = pack2(dA, dA);
        const ull dtx2 = pack2(dtx, dtx);
        ull y2 = pack2(0.f, 0.f);
        const ull* B2 = (const ull*)Bsh + nh * 16;
        const ull* C2 = (const ull*)Csh + nh * 16;
#pragma unroll
        for (int n = 0; n < 16; n++) {
            ull tb;
            MUL_X2(tb, dtx2, B2[n]);
            FMA_X2(h2[n], h2[n], dA2, tb);
            FMA_X2(y2, h2[n], C2[n], y2);
        }
        float ylo, yhi;
        asm("mov.b64 {%0, %1}, %2;" : "=f"(ylo), "=f"(yhi) : "l"(y2));
        float y = ylo + yhi;

        if (nh) ypar[chan] = y;
        __syncthreads();

        float g = 0.f;
        if (!nh) {
            y = fmaf(xv, Dhv, y + ypar[chan]);
            const float z = zbuf[t & 3][chan];
            g = y * (z / (1.f + expf(-z)));
            float ss = g * g;
#pragma unroll
            for (int o = 16; o; o >>= 1) ss += __shfl_xor_sync(0xffffffffu, ss, o);
            if ((tid & 31) == 0) red[tid >> 5] = ss;
        }
        __syncthreads();
        if (!nh) {
            float v = red[tid & 15];
#pragma unroll
            for (int o = 8; o; o >>= 1) v += __shfl_xor_sync(0xffffffffu, v, o);
            float s_inv = rsqrtf(v * (1.0f / 512.0f) + 1e-5f);
            float val = g * s_inv * nw;
            g_Y[(size_t)(base + t * stride) * KFIN + ycol_off + chan] = __float2half(val);
        }
    }
}

// ---------------- fold fc_w into out_w -----------------------------------------
__global__ void __launch_bounds__(256) wcomb_kernel(
    const float* __restrict__ mh_out_w, const float* __restrict__ mv_out_w,
    const float* __restrict__ fc_w)
{
    const int d  = blockIdx.x;
    const int k0 = blockIdx.y * 64;
    const int nb = blockIdx.z * 32;
    const float* ow = d ? mh_out_w : mv_out_w;
    const int fo = d ? 512 : 0;
    __shared__ float ows[64][65];
    __shared__ float fs[32][65];
    const int kk = threadIdx.x & 63;
    const int ng = threadIdx.x >> 6;
    float acc[8];
#pragma unroll
    for (int i = 0; i < 8; i++) acc[i] = 0.f;

    for (int jo = 0; jo < 256; jo += 64) {
        for (int idx = threadIdx.x; idx < 64 * 64; idx += 256) {
            int j = idx >> 6, c = idx & 63;
            ows[j][c] = ow[(size_t)(jo + j) * 512 + k0 + c];
        }
        for (int idx = threadIdx.x; idx < 32 * 64; idx += 256) {
            int n = idx >> 6, jj = idx & 63;
            fs[n][jj] = fc_w[(size_t)(nb + n) * 1024 + fo + jo + jj] +
                        fc_w[(size_t)(nb + n) * 1024 + fo + 256 + jo + jj];
        }
        __syncthreads();
#pragma unroll 4
        for (int j = 0; j < 64; j++) {
            float o = ows[j][kk];
#pragma unroll
            for (int i = 0; i < 8; i++)
                acc[i] = fmaf(o, fs[ng * 8 + i][j], acc[i]);
        }
        __syncthreads();
    }
#pragma unroll
    for (int i = 0; i < 8; i++) {
        float val = acc[i];
        __half hh = __float2half(val);
        size_t idx = (size_t)(nb + ng * 8 + i) * KFIN + d * 512 + (k0 + kk);
        g_WcBhi[idx] = hh;
        g_WcBlo[idx] = __float2half(val - __half2float(hh));
    }
}

// ---------------- launch ----------------
extern "C" void kernel_launch(void* const* d_in, const int* in_sizes, int n_in,
                              void* d_out, int out_size)
{
    (void)in_sizes; (void)n_in; (void)out_size;
    const float* x          = (const float*)d_in[0];
    const float* mh_in_w    = (const float*)d_in[1];
    const float* mh_conv_w  = (const float*)d_in[2];
    const float* mh_conv_b  = (const float*)d_in[3];
    const float* mh_dt_bias = (const float*)d_in[4];
    const float* mh_A_log   = (const float*)d_in[5];
    const float* mh_D       = (const float*)d_in[6];
    const float* mh_norm_w  = (const float*)d_in[7];
    const float* mh_out_w   = (const float*)d_in[8];
    const float* mv_in_w    = (const float*)d_in[9];
    const float* mv_conv_w  = (const float*)d_in[10];
    const float* mv_conv_b  = (const float*)d_in[11];
    const float* mv_dt_bias = (const float*)d_in[12];
    const float* mv_A_log   = (const float*)d_in[13];
    const float* mv_D       = (const float*)d_in[14];
    const float* mv_norm_w  = (const float*)d_in[15];
    const float* mv_out_w   = (const float*)d_in[16];
    const float* fc_w       = (const float*)d_in[17];
    const float* fc_b       = (const float*)d_in[18];
    float* out = (float*)d_out;

    float *Zh, *Zv;
    __half *Xhi, *Xlo, *Whhi, *Whlo, *Wvhi, *Wvlo, *Y, *WcBhi, *WcBlo;
    cudaGetSymbolAddress((void**)&Zh,   g_Zh);
    cudaGetSymbolAddress((void**)&Zv,   g_Zv);
    cudaGetSymbolAddress((void**)&Xhi,  g_Xhi);
    cudaGetSymbolAddress((void**)&Xlo,  g_Xlo);
    cudaGetSymbolAddress((void**)&Whhi, g_Whhi);
    cudaGetSymbolAddress((void**)&Whlo, g_Whlo);
    cudaGetSymbolAddress((void**)&Wvhi, g_Wvhi);
    cudaGetSymbolAddress((void**)&Wvlo, g_Wvlo);
    cudaGetSymbolAddress((void**)&Y,    g_Y);
    cudaGetSymbolAddress((void**)&WcBhi, g_WcBhi);
    cudaGetSymbolAddress((void**)&WcBlo, g_WcBlo);

    cudaFuncSetAttribute(gemm_mma, cudaFuncAttributeMaxDynamicSharedMemorySize, GSMEM);

    cvt_x_kernel<<<NTOK * D_MODEL / 4 / 256, 256>>>(x);
    prep_w_kernel<<<dim3((NPAD1 * D_MODEL + 255) / 256, 2), 256>>>(mh_in_w, mv_in_w);
    wcomb_kernel<<<dim3(2, 8, 8), 256>>>(mh_out_w, mv_out_w, fc_w);

    gemm_mma<<<dim3(NTOK / BMg, NPAD1 / BNg, 2), 256, GSMEM>>>(
        Xhi, Xlo, Whhi, Whlo, Wvhi, Wvlo, Zh, Zv, D_MODEL, NPAD1, nullptr, 1152);

    scan_kernel<<<2 * NSEQ, 1024>>>(
        mh_conv_w, mh_conv_b, mh_dt_bias, mh_A_log, mh_D, mh_norm_w,
        mv_conv_w, mv_conv_b, mv_dt_bias, mv_A_log, mv_D, mv_norm_w);

    gemm_mma<<<dim3(NTOK / BMg, D_MODEL / BNg, 1), 256, GSMEM>>>(
        Y, Y, WcBhi, WcBlo, WcBhi, WcBlo, out, out, KFIN, D_MODEL, fc_b, -1);
}

// round 10
// speedup vs baseline: 1.3562x; 1.3562x over previous
#include <cuda_runtime.h>
#include <cuda_bf16.h>
#include <cuda_fp16.h>
#include <math.h>
#include <stdint.h>

#define D_MODEL   256
#define D_INNER   512
#define CONV_CH   640
#define D_IN_PROJ 1160
#define NPAD1     1280
#define SEQ       64
#define NSEQ      512
#define NTOK      32768
#define KFIN      1024

// ---------------- scratch ------------------------------------------------------
__device__ float  g_Zh  [(size_t)NTOK * NPAD1];
__device__ float  g_Zv  [(size_t)NTOK * NPAD1];
__device__ __half g_Xhi [(size_t)NTOK * D_MODEL];
__device__ __half g_Xlo [(size_t)NTOK * D_MODEL];
__device__ __half g_Whhi[(size_t)NPAD1 * D_MODEL];
__device__ __half g_Whlo[(size_t)NPAD1 * D_MODEL];
__device__ __half g_Wvhi[(size_t)NPAD1 * D_MODEL];
__device__ __half g_Wvlo[(size_t)NPAD1 * D_MODEL];
__device__ __half g_Y   [(size_t)NTOK * KFIN];
__device__ __half g_WcBhi[(size_t)D_MODEL * KFIN];
__device__ __half g_WcBlo[(size_t)D_MODEL * KFIN];

// ---------------- helpers ------------------------------------------------------
__device__ __forceinline__ uint32_t smem_u32(const void* p) {
    uint32_t a;
    asm("{ .reg .u64 t; cvta.to.shared.u64 t, %1; cvt.u32.u64 %0, t; }" : "=r"(a) : "l"(p));
    return a;
}
__device__ __forceinline__ uint32_t sw64(uint32_t off) {   // 64B-row swizzle
    return off ^ ((off >> 3) & 0x30);
}
#define CP16(dst, src) \
    asm volatile("cp.async.cg.shared.global [%0], [%1], 16;" :: "r"(dst), "l"(src))
#define CP_COMMIT() asm volatile("cp.async.commit_group;" ::: "memory")
#define CP_WAIT(n)  asm volatile("cp.async.wait_group %0;" :: "n"(n) : "memory")

typedef unsigned long long ull;
__device__ __forceinline__ ull pack2(float lo, float hi) {
    ull r; asm("mov.b64 %0, {%1, %2};" : "=l"(r) : "f"(lo), "f"(hi)); return r;
}
#define FMA_X2(d, a, b, c) \
    asm("fma.rn.f32x2 %0, %1, %2, %3;" : "=l"(d) : "l"(a), "l"(b), "l"(c))
#define MUL_X2(d, a, b) \
    asm("mul.rn.f32x2 %0, %1, %2;" : "=l"(d) : "l"(a), "l"(b))

// ---------------- conversion kernels -------------------------------------------
__global__ void cvt_x_kernel(const float* __restrict__ in) {
    size_t i = (size_t)blockIdx.x * 256 + threadIdx.x;
    float4 v = ((const float4*)in)[i];
    __half h0 = __float2half(v.x), h1 = __float2half(v.y);
    __half h2 = __float2half(v.z), h3 = __float2half(v.w);
    __half2 hi01 = __halves2half2(h0, h1), hi23 = __halves2half2(h2, h3);
    __half2 lo01 = __halves2half2(__float2half(v.x - __half2float(h0)),
                                  __float2half(v.y - __half2float(h1)));
    __half2 lo23 = __halves2half2(__float2half(v.z - __half2float(h2)),
                                  __float2half(v.w - __half2float(h3)));
    ((__half2*)g_Xhi)[2 * i]     = hi01;
    ((__half2*)g_Xhi)[2 * i + 1] = hi23;
    ((__half2*)g_Xlo)[2 * i]     = lo01;
    ((__half2*)g_Xlo)[2 * i + 1] = lo23;
}

__global__ void prep_w_kernel(const float* __restrict__ wh, const float* __restrict__ wv) {
    int i = blockIdx.x * 256 + threadIdx.x;
    const float* w = blockIdx.y ? wv : wh;
    __half* whi = blockIdx.y ? g_Wvhi : g_Whhi;
    __half* wlo = blockIdx.y ? g_Wvlo : g_Whlo;
    if (i < NPAD1 * D_MODEL) {
        int n = i >> 8;
        float v = (n < D_IN_PROJ) ? w[i] : 0.f;
        __half h = __float2half(v);
        whi[i] = h;
        wlo[i] = __float2half(v - __half2float(h));
    }
}

// ---------------- mma.sync split-fp16 GEMM --------------------------------------
// nterms==1: C = A*Bhi   (dt tile upgraded to A*Bhi + A*Blo + Alo*Bhi)
// nterms==2: C = A*Bhi + A*Blo
#define BMg 128
#define BNg 128
#define TILE_Bg  8192
#define STAGE_Bg 32768
#define GSMEM    (3 * STAGE_Bg)

__global__ void __launch_bounds__(256, 2) gemm_mma(
    const __half* __restrict__ A, const __half* __restrict__ Alo,
    const __half* __restrict__ B0hi, const __half* __restrict__ B0lo,
    const __half* __restrict__ B1hi, const __half* __restrict__ B1lo,
    float* __restrict__ C0, float* __restrict__ C1,
    int K, int ldc, const float* __restrict__ bias, int dtn, int nterms)
{
    extern __shared__ __half sm[];
    const uint32_t smb = smem_u32(sm);
    const int tid = threadIdx.x, lane = tid & 31, wid = tid >> 5;
    const int m0 = blockIdx.x * BMg, n0 = blockIdx.y * BNg;
    const int wm = (wid & 1) * 64, wn = 32 * (wid >> 1);
    const int nk = K >> 5;
    const bool need3   = (n0 == dtn);
    const bool use_blo = (nterms == 2) || need3;

    const __half* Bhi = blockIdx.z ? B1hi : B0hi;
    const __half* Blo = blockIdx.z ? B1lo : B0lo;
    float* C = blockIdx.z ? C1 : C0;

    uint32_t arow[4], brow[2];
#pragma unroll
    for (int mt = 0; mt < 4; mt++)
        arow[mt] = (uint32_t)(wm + mt * 16 + (lane & 15)) * 64 + (lane >> 4) * 16;
#pragma unroll
    for (int nb = 0; nb < 2; nb++)
        brow[nb] = (uint32_t)(wn + nb * 16 + (lane & 15)) * 64 + (lane >> 4) * 16;

    float acc[4][4][4];
#pragma unroll
    for (int a = 0; a < 4; a++)
#pragma unroll
        for (int b = 0; b < 4; b++)
#pragma unroll
            for (int c = 0; c < 4; c++) acc[a][b][c] = 0.f;

    const int lrow = tid & 127, hf = tid >> 7;
    const uint32_t rb = (uint32_t)lrow * 64 + hf * 32;

    auto load_stage = [&](int s, int c) {
        const int koff = c * 32 + hf * 16;
        const uint32_t base = smb + s * STAGE_Bg;
        const __half* pA   = A   + (size_t)(m0 + lrow) * K + koff;
        const __half* pBhi = Bhi + (size_t)(n0 + lrow) * K + koff;
#pragma unroll
        for (int ch = 0; ch < 2; ch++) {
            uint32_t d = sw64(rb + ch * 16);
            CP16(base + d, pA + ch * 8);
            CP16(base + 2 * TILE_Bg + d, pBhi + ch * 8);
        }
        if (use_blo) {
            const __half* pBlo = Blo + (size_t)(n0 + lrow) * K + koff;
#pragma unroll
            for (int ch = 0; ch < 2; ch++)
                CP16(base + 3 * TILE_Bg + sw64(rb + ch * 16), pBlo + ch * 8);
        }
        if (need3) {
            const __half* pAlo = Alo + (size_t)(m0 + lrow) * K + koff;
#pragma unroll
            for (int ch = 0; ch < 2; ch++)
                CP16(base + TILE_Bg + sw64(rb + ch * 16), pAlo + ch * 8);
        }
        CP_COMMIT();
    };

    load_stage(0, 0);
    load_stage(1, 1);

    for (int c = 0; c < nk; c++) {
        if (c + 1 < nk) CP_WAIT(1); else CP_WAIT(0);
        __syncthreads();
        if (c + 2 < nk) load_stage((c + 2) % 3, c + 2);

        const uint32_t base = smb + (c % 3) * STAGE_Bg;
        const uint32_t aB = base, aLoB = base + TILE_Bg;
        const uint32_t bHiB = base + 2 * TILE_Bg, bLoB = base + 3 * TILE_Bg;
#pragma unroll
        for (int ks = 0; ks < 2; ks++) {
            uint32_t af[4][4], alo[4][4], bhi[2][4], blo[2][4];
#pragma unroll
            for (int mt = 0; mt < 4; mt++) {
                uint32_t sw = sw64(arow[mt] + ks * 32);
                asm volatile("ldmatrix.sync.aligned.m8n8.x4.shared.b16 {%0,%1,%2,%3}, [%4];"
                             : "=r"(af[mt][0]), "=r"(af[mt][1]), "=r"(af[mt][2]), "=r"(af[mt][3])
                             : "r"(aB + sw));
            }
#pragma unroll
            for (int nb = 0; nb < 2; nb++) {
                uint32_t sw = sw64(brow[nb] + ks * 32);
                asm volatile("ldmatrix.sync.aligned.m8n8.x4.shared.b16 {%0,%1,%2,%3}, [%4];"
                             : "=r"(bhi[nb][0]), "=r"(bhi[nb][1]), "=r"(bhi[nb][2]), "=r"(bhi[nb][3])
                             : "r"(bHiB + sw));
            }
            if (use_blo) {
#pragma unroll
                for (int nb = 0; nb < 2; nb++) {
                    uint32_t sw = sw64(brow[nb] + ks * 32);
                    asm volatile("ldmatrix.sync.aligned.m8n8.x4.shared.b16 {%0,%1,%2,%3}, [%4];"
                                 : "=r"(blo[nb][0]), "=r"(blo[nb][1]), "=r"(blo[nb][2]), "=r"(blo[nb][3])
                                 : "r"(bLoB + sw));
                }
            }
#define MMA_PASS(AF, BF)                                                              \
            _Pragma("unroll")                                                         \
            for (int mt = 0; mt < 4; mt++)                                            \
                _Pragma("unroll")                                                     \
                for (int nb = 0; nb < 2; nb++) {                                      \
                    asm volatile(                                                     \
                        "mma.sync.aligned.m16n8k16.row.col.f32.f16.f16.f32 "          \
                        "{%0,%1,%2,%3}, {%4,%5,%6,%7}, {%8,%9}, {%0,%1,%2,%3};"       \
                        : "+f"(acc[mt][nb * 2][0]), "+f"(acc[mt][nb * 2][1]),         \
                          "+f"(acc[mt][nb * 2][2]), "+f"(acc[mt][nb * 2][3])          \
                        : "r"(AF[mt][0]), "r"(AF[mt][1]), "r"(AF[mt][2]), "r"(AF[mt][3]), \
                          "r"(BF[nb][0]), "r"(BF[nb][2]));                            \
                    asm volatile(                                                     \
                        "mma.sync.aligned.m16n8k16.row.col.f32.f16.f16.f32 "          \
                        "{%0,%1,%2,%3}, {%4,%5,%6,%7}, {%8,%9}, {%0,%1,%2,%3};"       \
                        : "+f"(acc[mt][nb * 2 + 1][0]), "+f"(acc[mt][nb * 2 + 1][1]), \
                          "+f"(acc[mt][nb * 2 + 1][2]), "+f"(acc[mt][nb * 2 + 1][3])  \
                        : "r"(AF[mt][0]), "r"(AF[mt][1]), "r"(AF[mt][2]), "r"(AF[mt][3]), \
                          "r"(BF[nb][1]), "r"(BF[nb][3]));                            \
                }
            MMA_PASS(af, bhi)
            if (use_blo) { MMA_PASS(af, blo) }
            if (need3) {
#pragma unroll
                for (int mt = 0; mt < 4; mt++) {
                    uint32_t sw = sw64(arow[mt] + ks * 32);
                    asm volatile("ldmatrix.sync.aligned.m8n8.x4.shared.b16 {%0,%1,%2,%3}, [%4];"
                                 : "=r"(alo[mt][0]), "=r"(alo[mt][1]), "=r"(alo[mt][2]), "=r"(alo[mt][3])
                                 : "r"(aLoB + sw));
                }
                MMA_PASS(alo, bhi)
            }
#undef MMA_PASS
        }
    }

#pragma unroll
    for (int mt = 0; mt < 4; mt++) {
        int row = m0 + wm + mt * 16 + (lane >> 2);
#pragma unroll
        for (int nt = 0; nt < 4; nt++) {
            int col = n0 + wn + nt * 8 + (lane & 3) * 2;
            float2 v0 = make_float2(acc[mt][nt][0], acc[mt][nt][1]);
            float2 v1 = make_float2(acc[mt][nt][2], acc[mt][nt][3]);
            if (bias) {
                float b0 = bias[col], b1 = bias[col + 1];
                v0.x += b0; v0.y += b1; v1.x += b0; v1.y += b1;
            }
            *(float2*)&C[(size_t)row * ldc + col] = v0;
            *(float2*)&C[(size_t)(row + 8) * ldc + col] = v1;
        }
    }
}

// ---------------- fused conv + SiLU + softplus + SSM scan + gate + RMSnorm ------
// 512 threads (R8 shape) + deferred RMS-norm: output for step t written at t+1.
__global__ void __launch_bounds__(512, 1) scan_kernel(
    const float* __restrict__ cwh, const float* __restrict__ cbh,
    const float* __restrict__ dtbh, const float* __restrict__ Alh,
    const float* __restrict__ Dh_, const float* __restrict__ nwh,
    const float* __restrict__ cwv, const float* __restrict__ cbv,
    const float* __restrict__ dtbv, const float* __restrict__ Alv,
    const float* __restrict__ Dv_, const float* __restrict__ nwv)
{
    const int tid  = threadIdx.x;
    const int head = tid >> 6;
    const int dir  = blockIdx.x >> 9;
    const int s    = blockIdx.x & 511;

    const float* Z       = dir ? g_Zv : g_Zh;
    const float* conv_w  = dir ? cwv : cwh;
    const float* conv_b  = dir ? cbv : cbh;
    const float* dt_bias = dir ? dtbv : dtbh;
    const float* A_log   = dir ? Alv : Alh;
    const float* Dvv     = dir ? Dv_ : Dh_;
    const float* norm_w  = dir ? nwv : nwh;
    const int ycol_off   = dir ? 0 : 512;

    int base, stride;
    if (dir) { int b = s >> 6, w = s & 63; base = b * 4096 + w; stride = 64; }
    else     { base = s * 64; stride = 1; }

    __shared__ __align__(16) float ring[8][CONV_CH];
    __shared__ __align__(16) float zbuf[4][512];
    __shared__ __align__(16) float dtbuf[4][8];
    __shared__ __align__(16) float Bsh[64];
    __shared__ __align__(16) float Csh[64];
    __shared__ float dt_s[8], dA_s[8], Aneg_s[8], dtb_s[8];
    __shared__ float red[16];

    for (int i = tid; i < 8 * CONV_CH; i += 512) (&ring[0][0])[i] = 0.f;
    if (tid < 8) { Aneg_s[tid] = -expf(A_log[tid]); dtb_s[tid] = dt_bias[tid]; }

    const float w0 = conv_w[tid * 4 + 0], w1 = conv_w[tid * 4 + 1];
    const float w2 = conv_w[tid * 4 + 2], w3 = conv_w[tid * 4 + 3];
    const float cb = conv_b[tid];
    float u0 = 0.f, u1 = 0.f, u2 = 0.f, u3 = 0.f, cb2 = 0.f;
    const int c2 = 512 + tid;
    if (tid < 128) {
        u0 = conv_w[c2 * 4 + 0]; u1 = conv_w[c2 * 4 + 1];
        u2 = conv_w[c2 * 4 + 2]; u3 = conv_w[c2 * 4 + 3];
        cb2 = conv_b[c2];
    }
    const float Dhv = Dvv[head];
    const float nw = norm_w[tid];

    ull h2[32];
#pragma unroll
    for (int n = 0; n < 32; n++) h2[n] = pack2(0.f, 0.f);

    const uint32_t ring_b = smem_u32(&ring[0][0]);
    const uint32_t zbuf_b = smem_u32(&zbuf[0][0]);
    const uint32_t dtb_b  = smem_u32(&dtbuf[0][0]);

    auto prefetch = [&](int tt) {
        if (tt < SEQ) {
            const float* row = Z + (size_t)(base + tt * stride) * NPAD1;
            if (tid < 160)       CP16(ring_b + (tt & 7) * (CONV_CH * 4) + tid * 16, row + 512 + tid * 4);
            else if (tid < 288)  CP16(zbuf_b + (tt & 3) * 2048 + (tid - 160) * 16, row + (tid - 160) * 4);
            else if (tid < 290)  CP16(dtb_b + (tt & 3) * 32 + (tid - 288) * 16, row + 1152 + (tid - 288) * 4);
        }
        CP_COMMIT();
    };

    __syncthreads();
    prefetch(0);
    prefetch(1);

    float gprev = 0.f;
    size_t oidx_prev = 0;

    for (int t = 0; t < SEQ; t++) {
        if (t < SEQ - 1) CP_WAIT(1); else CP_WAIT(0);
        __syncthreads();

        // deferred output for step t-1 (red[] written before this barrier)
        if (t) {
            float v = red[tid & 15];
#pragma unroll
            for (int o = 8; o; o >>= 1) v += __shfl_xor_sync(0xffffffffu, v, o);
            float s_inv = rsqrtf(v * (1.0f / 512.0f) + 1e-5f);
            g_Y[oidx_prev] = __float2half(gprev * s_inv * nw);
        }

        prefetch(t + 2);

        const int slot = t & 7;
        if (tid < 8) {
            float draw = dtbuf[t & 3][tid] + dtb_s[tid];
            float dt = (draw > 20.f) ? draw : log1pf(expf(draw));
            dt_s[tid] = dt;
            dA_s[tid] = expf(dt * Aneg_s[tid]);
        }

        const int s0 = (t + 5) & 7, s1 = (t + 6) & 7, s2 = (t + 7) & 7, s3 = slot;
        float xv = cb;
        xv = fmaf(ring[s0][tid], w0, xv);
        xv = fmaf(ring[s1][tid], w1, xv);
        xv = fmaf(ring[s2][tid], w2, xv);
        xv = fmaf(ring[s3][tid], w3, xv);
        xv = xv / (1.f + expf(-xv));
        if (tid < 128) {
            float v = cb2;
            v = fmaf(ring[s0][c2], u0, v);
            v = fmaf(ring[s1][c2], u1, v);
            v = fmaf(ring[s2][c2], u2, v);
            v = fmaf(ring[s3][c2], u3, v);
            v = v / (1.f + expf(-v));
            if (tid < 64) Bsh[tid] = v; else Csh[tid - 64] = v;
        }
        __syncthreads();

        const float dA  = dA_s[head];
        const float dtx = dt_s[head] * xv;
        const ull dA2  = pack2(dA, dA);
        const ull dtx2 = pack2(dtx, dtx);
        ull y2 = pack2(0.f, 0.f);
        const ull* B2 = (const ull*)Bsh;
        const ull* C2 = (const ull*)Csh;
#pragma unroll
        for (int n = 0; n < 32; n++) {
            ull tb;
            MUL_X2(tb, dtx2, B2[n]);
            FMA_X2(h2[n], h2[n], dA2, tb);
            FMA_X2(y2, h2[n], C2[n], y2);
        }
        float ylo, yhi;
        asm("mov.b64 {%0, %1}, %2;" : "=f"(ylo), "=f"(yhi) : "l"(y2));
        float y = ylo + yhi;
        y = fmaf(xv, Dhv, y);

        const float z = zbuf[t & 3][tid];
        float g = y * (z / (1.f + expf(-z)));
        float ss = g * g;
#pragma unroll
        for (int o = 16; o; o >>= 1) ss += __shfl_xor_sync(0xffffffffu, ss, o);
        if ((tid & 31) == 0) red[tid >> 5] = ss;

        gprev = g;
        oidx_prev = (size_t)(base + t * stride) * KFIN + ycol_off + tid;
    }

    // epilogue: output for final step
    __syncthreads();
    {
        float v = red[tid & 15];
#pragma unroll
        for (int o = 8; o; o >>= 1) v += __shfl_xor_sync(0xffffffffu, v, o);
        float s_inv = rsqrtf(v * (1.0f / 512.0f) + 1e-5f);
        g_Y[oidx_prev] = __float2half(gprev * s_inv * nw);
    }
}

// ---------------- fold fc_w into out_w -----------------------------------------
__global__ void __launch_bounds__(256) wcomb_kernel(
    const float* __restrict__ mh_out_w, const float* __restrict__ mv_out_w,
    const float* __restrict__ fc_w)
{
    const int d  = blockIdx.x;
    const int k0 = blockIdx.y * 64;
    const int nb = blockIdx.z * 32;
    const float* ow = d ? mh_out_w : mv_out_w;
    const int fo = d ? 512 : 0;
    __shared__ float ows[64][65];
    __shared__ float fs[32][65];
    const int kk = threadIdx.x & 63;
    const int ng = threadIdx.x >> 6;
    float acc[8];
#pragma unroll
    for (int i = 0; i < 8; i++) acc[i] = 0.f;

    for (int jo = 0; jo < 256; jo += 64) {
        for (int idx = threadIdx.x; idx < 64 * 64; idx += 256) {
            int j = idx >> 6, c = idx & 63;
            ows[j][c] = ow[(size_t)(jo + j) * 512 + k0 + c];
        }
        for (int idx = threadIdx.x; idx < 32 * 64; idx += 256) {
            int n = idx >> 6, jj = idx & 63;
            fs[n][jj] = fc_w[(size_t)(nb + n) * 1024 + fo + jo + jj] +
                        fc_w[(size_t)(nb + n) * 1024 + fo + 256 + jo + jj];
        }
        __syncthreads();
#pragma unroll 4
        for (int j = 0; j < 64; j++) {
            float o = ows[j][kk];
#pragma unroll
            for (int i = 0; i < 8; i++)
                acc[i] = fmaf(o, fs[ng * 8 + i][j], acc[i]);
        }
        __syncthreads();
    }
#pragma unroll
    for (int i = 0; i < 8; i++) {
        float val = acc[i];
        __half hh = __float2half(val);
        size_t idx = (size_t)(nb + ng * 8 + i) * KFIN + d * 512 + (k0 + kk);
        g_WcBhi[idx] = hh;
        g_WcBlo[idx] = __float2half(val - __half2float(hh));
    }
}

// ---------------- launch ----------------
extern "C" void kernel_launch(void* const* d_in, const int* in_sizes, int n_in,
                              void* d_out, int out_size)
{
    (void)in_sizes; (void)n_in; (void)out_size;
    const float* x          = (const float*)d_in[0];
    const float* mh_in_w    = (const float*)d_in[1];
    const float* mh_conv_w  = (const float*)d_in[2];
    const float* mh_conv_b  = (const float*)d_in[3];
    const float* mh_dt_bias = (const float*)d_in[4];
    const float* mh_A_log   = (const float*)d_in[5];
    const float* mh_D       = (const float*)d_in[6];
    const float* mh_norm_w  = (const float*)d_in[7];
    const float* mh_out_w   = (const float*)d_in[8];
    const float* mv_in_w    = (const float*)d_in[9];
    const float* mv_conv_w  = (const float*)d_in[10];
    const float* mv_conv_b  = (const float*)d_in[11];
    const float* mv_dt_bias = (const float*)d_in[12];
    const float* mv_A_log   = (const float*)d_in[13];
    const float* mv_D       = (const float*)d_in[14];
    const float* mv_norm_w  = (const float*)d_in[15];
    const float* mv_out_w   = (const float*)d_in[16];
    const float* fc_w       = (const float*)d_in[17];
    const float* fc_b       = (const float*)d_in[18];
    float* out = (float*)d_out;

    float *Zh, *Zv;
    __half *Xhi, *Xlo, *Whhi, *Whlo, *Wvhi, *Wvlo, *Y, *WcBhi, *WcBlo;
    cudaGetSymbolAddress((void**)&Zh,   g_Zh);
    cudaGetSymbolAddress((void**)&Zv,   g_Zv);
    cudaGetSymbolAddress((void**)&Xhi,  g_Xhi);
    cudaGetSymbolAddress((void**)&Xlo,  g_Xlo);
    cudaGetSymbolAddress((void**)&Whhi, g_Whhi);
    cudaGetSymbolAddress((void**)&Whlo, g_Whlo);
    cudaGetSymbolAddress((void**)&Wvhi, g_Wvhi);
    cudaGetSymbolAddress((void**)&Wvlo, g_Wvlo);
    cudaGetSymbolAddress((void**)&Y,    g_Y);
    cudaGetSymbolAddress((void**)&WcBhi, g_WcBhi);
    cudaGetSymbolAddress((void**)&WcBlo, g_WcBlo);

    cudaFuncSetAttribute(gemm_mma, cudaFuncAttributeMaxDynamicSharedMemorySize, GSMEM);

    cvt_x_kernel<<<NTOK * D_MODEL / 4 / 256, 256>>>(x);
    prep_w_kernel<<<dim3((NPAD1 * D_MODEL + 255) / 256, 2), 256>>>(mh_in_w, mv_in_w);
    wcomb_kernel<<<dim3(2, 8, 8), 256>>>(mh_out_w, mv_out_w, fc_w);

    // in-proj: 1-term fp16 (dt tile n0=1152 gets 3-term treatment)
    gemm_mma<<<dim3(NTOK / BMg, NPAD1 / BNg, 2), 256, GSMEM>>>(
        Xhi, Xlo, Whhi, Whlo, Wvhi, Wvlo, Zh, Zv, D_MODEL, NPAD1, nullptr, 1152, 1);

    scan_kernel<<<2 * NSEQ, 512>>>(
        mh_conv_w, mh_conv_b, mh_dt_bias, mh_A_log, mh_D, mh_norm_w,
        mv_conv_w, mv_conv_b, mv_dt_bias, mv_A_log, mv_D, mv_norm_w);

    // final output GEMM: 2-term
    gemm_mma<<<dim3(NTOK / BMg, D_MODEL / BNg, 1), 256, GSMEM>>>(
        Y, Y, WcBhi, WcBlo, WcBhi, WcBlo, out, out, KFIN, D_MODEL, fc_b, -1, 2);
}

// round 12
// speedup vs baseline: 1.8070x; 1.3325x over previous
#include <cuda_runtime.h>
#include <cuda_bf16.h>
#include <cuda_fp16.h>
#include <math.h>
#include <stdint.h>

#define D_MODEL   256
#define D_INNER   512
#define CONV_CH   640
#define D_IN_PROJ 1160
#define NPAD1     1280
#define SEQ       64
#define NSEQ      512
#define NTOK      32768
#define KFIN      1024

// ---------------- scratch ------------------------------------------------------
__device__ float  g_Zh  [(size_t)NTOK * NPAD1];
__device__ float  g_Zv  [(size_t)NTOK * NPAD1];
__device__ __half g_XBCh[(size_t)NTOK * CONV_CH];
__device__ __half g_XBCv[(size_t)NTOK * CONV_CH];
__device__ __half g_Xhi [(size_t)NTOK * D_MODEL];
__device__ __half g_Xlo [(size_t)NTOK * D_MODEL];
__device__ __half g_Whhi[(size_t)NPAD1 * D_MODEL];
__device__ __half g_Whlo[(size_t)NPAD1 * D_MODEL];
__device__ __half g_Wvhi[(size_t)NPAD1 * D_MODEL];
__device__ __half g_Wvlo[(size_t)NPAD1 * D_MODEL];
__device__ __half g_Y   [(size_t)NTOK * KFIN];
__device__ __half g_WcBhi[(size_t)D_MODEL * KFIN];
__device__ __half g_WcBlo[(size_t)D_MODEL * KFIN];

extern __shared__ char dynsm[];

// ---------------- helpers ------------------------------------------------------
__device__ __forceinline__ uint32_t smem_u32(const void* p) {
    uint32_t a;
    asm("{ .reg .u64 t; cvta.to.shared.u64 t, %1; cvt.u32.u64 %0, t; }" : "=r"(a) : "l"(p));
    return a;
}
__device__ __forceinline__ uint32_t sw64(uint32_t off) {
    return off ^ ((off >> 3) & 0x30);
}
#define CP16(dst, src) \
    asm volatile("cp.async.cg.shared.global [%0], [%1], 16;" :: "r"(dst), "l"(src))
#define CP_COMMIT() asm volatile("cp.async.commit_group;" ::: "memory")
#define CP_WAIT(n)  asm volatile("cp.async.wait_group %0;" :: "n"(n) : "memory")

__device__ __forceinline__ void ldm4(uint32_t* r, uint32_t addr) {
    asm volatile("ldmatrix.sync.aligned.m8n8.x4.shared.b16 {%0,%1,%2,%3}, [%4];"
        : "=r"(r[0]), "=r"(r[1]), "=r"(r[2]), "=r"(r[3]) : "r"(addr));
}
__device__ __forceinline__ void mma16816(float* d, const uint32_t* a, uint32_t b0, uint32_t b1) {
    asm volatile("mma.sync.aligned.m16n8k16.row.col.f32.f16.f16.f32 "
        "{%0,%1,%2,%3}, {%4,%5,%6,%7}, {%8,%9}, {%0,%1,%2,%3};"
        : "+f"(d[0]), "+f"(d[1]), "+f"(d[2]), "+f"(d[3])
        : "r"(a[0]), "r"(a[1]), "r"(a[2]), "r"(a[3]), "r"(b0), "r"(b1));
}

// ---------------- conversion kernels -------------------------------------------
__global__ void cvt_x_kernel(const float* __restrict__ in) {
    size_t i = (size_t)blockIdx.x * 256 + threadIdx.x;
    float4 v = ((const float4*)in)[i];
    __half h0 = __float2half(v.x), h1 = __float2half(v.y);
    __half h2 = __float2half(v.z), h3 = __float2half(v.w);
    __half2 hi01 = __halves2half2(h0, h1), hi23 = __halves2half2(h2, h3);
    __half2 lo01 = __halves2half2(__float2half(v.x - __half2float(h0)),
                                  __float2half(v.y - __half2float(h1)));
    __half2 lo23 = __halves2half2(__float2half(v.z - __half2float(h2)),
                                  __float2half(v.w - __half2float(h3)));
    ((__half2*)g_Xhi)[2 * i]     = hi01;
    ((__half2*)g_Xhi)[2 * i + 1] = hi23;
    ((__half2*)g_Xlo)[2 * i]     = lo01;
    ((__half2*)g_Xlo)[2 * i + 1] = lo23;
}

__global__ void prep_w_kernel(const float* __restrict__ wh, const float* __restrict__ wv) {
    int i = blockIdx.x * 256 + threadIdx.x;
    const float* w = blockIdx.y ? wv : wh;
    __half* whi = blockIdx.y ? g_Wvhi : g_Whhi;
    __half* wlo = blockIdx.y ? g_Wvlo : g_Whlo;
    if (i < NPAD1 * D_MODEL) {
        int n = i >> 8;
        float v = (n < D_IN_PROJ) ? w[i] : 0.f;
        __half h = __float2half(v);
        whi[i] = h;
        wlo[i] = __float2half(v - __half2float(h));
    }
}

// ---------------- mma.sync split-fp16 GEMM --------------------------------------
#define BMg 128
#define BNg 128
#define TILE_Bg  8192
#define STAGE_Bg 32768
#define GSMEM    (3 * STAGE_Bg)

__global__ void __launch_bounds__(256, 2) gemm_mma(
    const __half* __restrict__ A, const __half* __restrict__ Alo,
    const __half* __restrict__ B0hi, const __half* __restrict__ B0lo,
    const __half* __restrict__ B1hi, const __half* __restrict__ B1lo,
    float* __restrict__ C0, float* __restrict__ C1,
    __half* __restrict__ X0, __half* __restrict__ X1,
    int K, int ldc, const float* __restrict__ bias, int dtn, int nterms)
{
    const uint32_t smb = smem_u32(dynsm);
    const int tid = threadIdx.x, lane = tid & 31, wid = tid >> 5;
    const int m0 = blockIdx.x * BMg, n0 = blockIdx.y * BNg;
    const int wm = (wid & 1) * 64, wn = 32 * (wid >> 1);
    const int nk = K >> 5;
    const bool need3   = (n0 == dtn);
    const bool use_blo = (nterms == 2) || need3;
    const bool toXBC   = (dtn == 1152) && (n0 >= 512) && (n0 < 1152);

    const __half* Bhi = blockIdx.z ? B1hi : B0hi;
    const __half* Blo = blockIdx.z ? B1lo : B0lo;
    float* C = blockIdx.z ? C1 : C0;
    __half* XB = blockIdx.z ? X1 : X0;

    uint32_t arow[4], brow[2];
#pragma unroll
    for (int mt = 0; mt < 4; mt++)
        arow[mt] = (uint32_t)(wm + mt * 16 + (lane & 15)) * 64 + (lane >> 4) * 16;
#pragma unroll
    for (int nb = 0; nb < 2; nb++)
        brow[nb] = (uint32_t)(wn + nb * 16 + (lane & 15)) * 64 + (lane >> 4) * 16;

    float acc[4][4][4];
#pragma unroll
    for (int a = 0; a < 4; a++)
#pragma unroll
        for (int b = 0; b < 4; b++)
#pragma unroll
            for (int c = 0; c < 4; c++) acc[a][b][c] = 0.f;

    const int lrow = tid & 127, hf = tid >> 7;
    const uint32_t rb = (uint32_t)lrow * 64 + hf * 32;

    auto load_stage = [&](int s, int c) {
        const int koff = c * 32 + hf * 16;
        const uint32_t base = smb + s * STAGE_Bg;
        const __half* pA   = A   + (size_t)(m0 + lrow) * K + koff;
        const __half* pBhi = Bhi + (size_t)(n0 + lrow) * K + koff;
#pragma unroll
        for (int ch = 0; ch < 2; ch++) {
            uint32_t d = sw64(rb + ch * 16);
            CP16(base + d, pA + ch * 8);
            CP16(base + 2 * TILE_Bg + d, pBhi + ch * 8);
        }
        if (use_blo) {
            const __half* pBlo = Blo + (size_t)(n0 + lrow) * K + koff;
#pragma unroll
            for (int ch = 0; ch < 2; ch++)
                CP16(base + 3 * TILE_Bg + sw64(rb + ch * 16), pBlo + ch * 8);
        }
        if (need3) {
            const __half* pAlo = Alo + (size_t)(m0 + lrow) * K + koff;
#pragma unroll
            for (int ch = 0; ch < 2; ch++)
                CP16(base + TILE_Bg + sw64(rb + ch * 16), pAlo + ch * 8);
        }
        CP_COMMIT();
    };

    load_stage(0, 0);
    load_stage(1, 1);

    for (int c = 0; c < nk; c++) {
        if (c + 1 < nk) CP_WAIT(1); else CP_WAIT(0);
        __syncthreads();
        if (c + 2 < nk) load_stage((c + 2) % 3, c + 2);

        const uint32_t base = smb + (c % 3) * STAGE_Bg;
        const uint32_t aB = base, aLoB = base + TILE_Bg;
        const uint32_t bHiB = base + 2 * TILE_Bg, bLoB = base + 3 * TILE_Bg;
#pragma unroll
        for (int ks = 0; ks < 2; ks++) {
            uint32_t af[4][4], alo[4][4], bhi[2][4], blo[2][4];
#pragma unroll
            for (int mt = 0; mt < 4; mt++)
                ldm4(af[mt], aB + sw64(arow[mt] + ks * 32));
#pragma unroll
            for (int nb = 0; nb < 2; nb++)
                ldm4(bhi[nb], bHiB + sw64(brow[nb] + ks * 32));
            if (use_blo) {
#pragma unroll
                for (int nb = 0; nb < 2; nb++)
                    ldm4(blo[nb], bLoB + sw64(brow[nb] + ks * 32));
            }
#pragma unroll
            for (int mt = 0; mt < 4; mt++)
#pragma unroll
                for (int nb = 0; nb < 2; nb++) {
                    mma16816(acc[mt][nb * 2],     af[mt], bhi[nb][0], bhi[nb][2]);
                    mma16816(acc[mt][nb * 2 + 1], af[mt], bhi[nb][1], bhi[nb][3]);
                }
            if (use_blo) {
#pragma unroll
                for (int mt = 0; mt < 4; mt++)
#pragma unroll
                    for (int nb = 0; nb < 2; nb++) {
                        mma16816(acc[mt][nb * 2],     af[mt], blo[nb][0], blo[nb][2]);
                        mma16816(acc[mt][nb * 2 + 1], af[mt], blo[nb][1], blo[nb][3]);
                    }
            }
            if (need3) {
#pragma unroll
                for (int mt = 0; mt < 4; mt++)
                    ldm4(alo[mt], aLoB + sw64(arow[mt] + ks * 32));
#pragma unroll
                for (int mt = 0; mt < 4; mt++)
#pragma unroll
                    for (int nb = 0; nb < 2; nb++) {
                        mma16816(acc[mt][nb * 2],     alo[mt], bhi[nb][0], bhi[nb][2]);
                        mma16816(acc[mt][nb * 2 + 1], alo[mt], bhi[nb][1], bhi[nb][3]);
                    }
            }
        }
    }

#pragma unroll
    for (int mt = 0; mt < 4; mt++) {
        int row = m0 + wm + mt * 16 + (lane >> 2);
#pragma unroll
        for (int nt = 0; nt < 4; nt++) {
            int col = n0 + wn + nt * 8 + (lane & 3) * 2;
            float2 v0 = make_float2(acc[mt][nt][0], acc[mt][nt][1]);
            float2 v1 = make_float2(acc[mt][nt][2], acc[mt][nt][3]);
            if (toXBC) {
                int xc = col - 512;
                *(__half2*)&XB[(size_t)row * 640 + xc]       = __floats2half2_rn(v0.x, v0.y);
                *(__half2*)&XB[(size_t)(row + 8) * 640 + xc] = __floats2half2_rn(v1.x, v1.y);
            } else {
                if (bias) {
                    float b0 = bias[col], b1 = bias[col + 1];
                    v0.x += b0; v0.y += b1; v1.x += b0; v1.y += b1;
                }
                *(float2*)&C[(size_t)row * ldc + col] = v0;
                *(float2*)&C[(size_t)(row + 8) * ldc + col] = v1;
            }
        }
    }
}

// ---------------- SSD kernel: conv + SiLU + scan-as-GEMM + gate + RMSnorm -------
#define RAW_PITCH 1296
#define XDT_PITCH 144
#define G_PITCH   68
#define GSM_PITCH 520

#define RAW_OFF   0
#define GSM_OFF   0
#define XDT_OFF   86832
#define BM_OFF    160560
#define CM_OFF    169776
#define G_OFF     178992
#define GMH_OFF   196400
#define GML_OFF   205616
#define L_OFF     214832
#define DTS_OFF   216880
#define DDT_OFF   218928
#define NW_OFF    220976
#define SSD_SMEM  223040

__global__ void __launch_bounds__(512, 1) ssd_kernel(
    const float* __restrict__ cwh, const float* __restrict__ cbh,
    const float* __restrict__ dtbh, const float* __restrict__ Alh,
    const float* __restrict__ Dh_, const float* __restrict__ nwh,
    const float* __restrict__ cwv, const float* __restrict__ cbv,
    const float* __restrict__ dtbv, const float* __restrict__ Alv,
    const float* __restrict__ Dv_, const float* __restrict__ nwv)
{
    char* sm = dynsm;
    const uint32_t smb = smem_u32(sm);
    const int tid = threadIdx.x, lane = tid & 31, wid = tid >> 5;
    const int dir = blockIdx.x >> 9;
    const int s   = blockIdx.x & 511;

    const float*  Z       = dir ? g_Zv : g_Zh;
    const __half* XBC     = dir ? g_XBCv : g_XBCh;
    const float*  conv_w  = dir ? cwv : cwh;
    const float*  conv_b  = dir ? cbv : cbh;
    const float*  dt_bias = dir ? dtbv : dtbh;
    const float*  A_log   = dir ? Alv : Alh;
    const float*  Dv      = dir ? Dv_ : Dh_;
    const float*  norm_w  = dir ? nwv : nwh;
    const int ycol = dir ? 0 : 512;

    int base, stride;
    if (dir) { int b = s >> 6, w = s & 63; base = b * 4096 + w; stride = 64; }
    else     { base = s * 64; stride = 1; }

    __half* XdT = (__half*)(sm + XDT_OFF);
    __half* Bm  = (__half*)(sm + BM_OFF);
    __half* Cm  = (__half*)(sm + CM_OFF);
    float*  G   = (float*)(sm + G_OFF);
    float*  Lc  = (float*)(sm + L_OFF);
    float*  dts = (float*)(sm + DTS_OFF);
    float*  Ddt = (float*)(sm + DDT_OFF);
    float*  nws = (float*)(sm + NW_OFF);
    __half* gsm = (__half*)(sm + GSM_OFF);

    nws[tid] = norm_w[tid];
    ((uint32_t*)sm)[tid] = 0;
    if (tid < 460) ((uint32_t*)sm)[tid + 512] = 0;

    // stage raw xBC (fp16, 64 rows x 1280 B) into RAW rows 3..66
#pragma unroll
    for (int j = 0; j < 10; j++) {
        int idx = tid + j * 512;
        int row = idx / 80, c16 = idx % 80;
        uint32_t dst = smb + RAW_OFF + (uint32_t)(row + 3) * RAW_PITCH + c16 * 16;
        const __half* src = XBC + (size_t)(base + row * stride) * 640 + c16 * 8;
        CP16(dst, src);
    }
    CP_COMMIT();

    // dt / cumsum: warp h handles head h
    if (wid < 8) {
        const int h = wid;
        const float Aneg = -__expf(A_log[h]);
        const float dtb = dt_bias[h];
        const float Dh = Dv[h];
        float v0, v1;
        {
            int t = lane;
            float draw = Z[(size_t)(base + t * stride) * NPAD1 + 1152 + h] + dtb;
            float dt = (draw > 20.f) ? draw : log1pf(__expf(draw));
            dts[h * 64 + t] = dt; Ddt[h * 64 + t] = Dh / dt;
            v0 = dt * Aneg;
        }
        {
            int t = lane + 32;
            float draw = Z[(size_t)(base + t * stride) * NPAD1 + 1152 + h] + dtb;
            float dt = (draw > 20.f) ? draw : log1pf(__expf(draw));
            dts[h * 64 + t] = dt; Ddt[h * 64 + t] = Dh / dt;
            v1 = dt * Aneg;
        }
        float a = v0;
#pragma unroll
        for (int o = 1; o < 32; o <<= 1) {
            float u = __shfl_up_sync(0xffffffffu, a, o);
            if (lane >= o) a += u;
        }
        float tot = __shfl_sync(0xffffffffu, a, 31);
        float b = v1;
#pragma unroll
        for (int o = 1; o < 32; o <<= 1) {
            float u = __shfl_up_sync(0xffffffffu, b, o);
            if (lane >= o) b += u;
        }
        b += tot;
        Lc[h * 64 + lane] = a;
        Lc[h * 64 + 32 + lane] = b;
    }
    CP_WAIT(0);
    __syncthreads();

    // conv + SiLU
    {
        const int c = tid, hd = c >> 6;
        const float w0 = conv_w[c * 4], w1 = conv_w[c * 4 + 1];
        const float w2 = conv_w[c * 4 + 2], w3 = conv_w[c * 4 + 3];
        const float cb = conv_b[c];
        const bool isbc = (tid < 128);
        const int c2 = 512 + tid;
        float u0 = 0, u1 = 0, u2 = 0, u3 = 0, ub = 0;
        __half* dstBC = (tid < 64) ? (Bm + tid) : (Cm + (tid - 64));
        if (isbc) {
            u0 = conv_w[c2 * 4]; u1 = conv_w[c2 * 4 + 1];
            u2 = conv_w[c2 * 4 + 2]; u3 = conv_w[c2 * 4 + 3];
            ub = conv_b[c2];
        }
        float r0 = 0, r1 = 0, r2 = 0, q0 = 0, q1 = 0, q2 = 0;
        for (int t = 0; t < SEQ; t++) {
            float cur = __half2float(*(__half*)(sm + RAW_OFF + (t + 3) * RAW_PITCH + c * 2));
            float v = fmaf(cur, w3, fmaf(r2, w2, fmaf(r1, w1, fmaf(r0, w0, cb))));
            r0 = r1; r1 = r2; r2 = cur;
            v = v / (1.f + __expf(-v));
            XdT[c * 72 + t] = __float2half(v * dts[hd * 64 + t]);
            if (isbc) {
                float cq = __half2float(*(__half*)(sm + RAW_OFF + (t + 3) * RAW_PITCH + c2 * 2));
                float vq = fmaf(cq, u3, fmaf(q2, u2, fmaf(q1, u1, fmaf(q0, u0, ub))));
                q0 = q1; q1 = q2; q2 = cq;
                vq = vq / (1.f + __expf(-vq));
                dstBC[t * 72] = __float2half(vq);
            }
        }
    }
    __syncthreads();

    // G = C @ B^T (64x64x64)
    const int mi = wid & 3, nj = wid >> 2;
    {
        float acc[2][4];
#pragma unroll
        for (int i = 0; i < 2; i++)
#pragma unroll
            for (int j = 0; j < 4; j++) acc[i][j] = 0.f;
#pragma unroll
        for (int ks = 0; ks < 4; ks++) {
            uint32_t a[4], bq[4];
            ldm4(a,  smb + CM_OFF + (mi * 16 + (lane & 15)) * XDT_PITCH + (lane >> 4) * 16 + ks * 32);
            ldm4(bq, smb + BM_OFF + (nj * 16 + (lane & 15)) * XDT_PITCH + (lane >> 4) * 16 + ks * 32);
            mma16816(acc[0], a, bq[0], bq[2]);
            mma16816(acc[1], a, bq[1], bq[3]);
        }
        const int r = lane >> 2, cc = (lane & 3) * 2;
#pragma unroll
        for (int nt = 0; nt < 2; nt++) {
            int sc = nj * 16 + nt * 8 + cc;
            *(float2*)&G[(mi * 16 + r) * G_PITCH + sc]     = make_float2(acc[nt][0], acc[nt][1]);
            *(float2*)&G[(mi * 16 + r + 8) * G_PITCH + sc] = make_float2(acc[nt][2], acc[nt][3]);
        }
    }
    __syncthreads();

    // per-head masked GEMMs
    for (int h = 0; h < 8; h++) {
        const float* Lh = Lc + h * 64;
        __half* Gmh = (__half*)(sm + GMH_OFF);
        __half* Gml = (__half*)(sm + GML_OFF);
#pragma unroll
        for (int k = 0; k < 8; k++) {
            int idx = tid + k * 512;
            int t = idx >> 6, sc = idx & 63;
            float w = 0.f;
            if (sc <= t) w = __expf(Lh[t] - Lh[sc]);
            float gm = G[t * G_PITCH + sc] * w;
            if (sc == t) gm += Ddt[h * 64 + t];
            __half hi = __float2half(gm);
            Gmh[t * 72 + sc] = hi;
            Gml[t * 72 + sc] = __float2half(gm - __half2float(hi));
        }
        __syncthreads();

        float acc[2][4];
#pragma unroll
        for (int i = 0; i < 2; i++)
#pragma unroll
            for (int j = 0; j < 4; j++) acc[i][j] = 0.f;
#pragma unroll
        for (int ks = 0; ks < 4; ks++) {
            uint32_t ah[4], al[4], bq[4];
            uint32_t ro = (mi * 16 + (lane & 15)) * XDT_PITCH + (lane >> 4) * 16 + ks * 32;
            ldm4(ah, smb + GMH_OFF + ro);
            ldm4(al, smb + GML_OFF + ro);
            ldm4(bq, smb + XDT_OFF + (uint32_t)(h * 64 + nj * 16 + (lane & 15)) * XDT_PITCH
                        + (lane >> 4) * 16 + ks * 32);
            mma16816(acc[0], ah, bq[0], bq[2]);
            mma16816(acc[1], ah, bq[1], bq[3]);
            mma16816(acc[0], al, bq[0], bq[2]);
            mma16816(acc[1], al, bq[1], bq[3]);
        }
        const int r = lane >> 2, cc = (lane & 3) * 2;
#pragma unroll
        for (int nt = 0; nt < 2; nt++)
#pragma unroll
            for (int rr = 0; rr < 2; rr++) {
                int t = mi * 16 + r + rr * 8;
                int p = nj * 16 + nt * 8 + cc;
                float y0 = acc[nt][rr * 2 + 0], y1 = acc[nt][rr * 2 + 1];
                size_t zi = (size_t)(base + t * stride) * NPAD1 + h * 64 + p;
                float z0 = Z[zi], z1 = Z[zi + 1];
                float g0 = y0 * z0 / (1.f + __expf(-z0));
                float g1 = y1 * z1 / (1.f + __expf(-z1));
                *(__half2*)&gsm[t * GSM_PITCH + h * 64 + p] = __floats2half2_rn(g0, g1);
            }
        __syncthreads();
    }

    // RMS norm + output
#pragma unroll
    for (int k = 0; k < 4; k++) {
        int t = wid + k * 16;
        float ss = 0.f;
        float2 gv[8];
#pragma unroll
        for (int j = 0; j < 8; j++) {
            __half2 hv = *(__half2*)&gsm[t * GSM_PITCH + j * 64 + lane * 2];
            float a = __half2float(hv.x), b = __half2float(hv.y);
            gv[j] = make_float2(a, b);
            ss = fmaf(a, a, ss); ss = fmaf(b, b, ss);
        }
#pragma unroll
        for (int o = 16; o; o >>= 1) ss += __shfl_xor_sync(0xffffffffu, ss, o);
        float sinv = rsqrtf(ss * (1.0f / 512.0f) + 1e-5f);
        size_t orow = (size_t)(base + t * stride) * KFIN + ycol;
#pragma unroll
        for (int j = 0; j < 8; j++) {
            int c = j * 64 + lane * 2;
            float a = gv[j].x * sinv * nws[c];
            float b = gv[j].y * sinv * nws[c + 1];
            *(__half2*)&g_Y[orow + c] = __floats2half2_rn(a, b);
        }
    }
}

// ---------------- fold fc_w into out_w -----------------------------------------
__global__ void __launch_bounds__(256) wcomb_kernel(
    const float* __restrict__ mh_out_w, const float* __restrict__ mv_out_w,
    const float* __restrict__ fc_w)
{
    const int d  = blockIdx.x;
    const int k0 = blockIdx.y * 64;
    const int nb = blockIdx.z * 32;
    const float* ow = d ? mh_out_w : mv_out_w;
    const int fo = d ? 512 : 0;
    __shared__ float ows[64][65];
    __shared__ float fs[32][65];
    const int kk = threadIdx.x & 63;
    const int ng = threadIdx.x >> 6;
    float acc[8];
#pragma unroll
    for (int i = 0; i < 8; i++) acc[i] = 0.f;

    for (int jo = 0; jo < 256; jo += 64) {
        for (int idx = threadIdx.x; idx < 64 * 64; idx += 256) {
            int j = idx >> 6, c = idx & 63;
            ows[j][c] = ow[(size_t)(jo + j) * 512 + k0 + c];
        }
        for (int idx = threadIdx.x; idx < 32 * 64; idx += 256) {
            int n = idx >> 6, jj = idx & 63;
            fs[n][jj] = fc_w[(size_t)(nb + n) * 1024 + fo + jo + jj] +
                        fc_w[(size_t)(nb + n) * 1024 + fo + 256 + jo + jj];
        }
        __syncthreads();
#pragma unroll 4
        for (int j = 0; j < 64; j++) {
            float o = ows[j][kk];
#pragma unroll
            for (int i = 0; i < 8; i++)
                acc[i] = fmaf(o, fs[ng * 8 + i][j], acc[i]);
        }
        __syncthreads();
    }
#pragma unroll
    for (int i = 0; i < 8; i++) {
        float val = acc[i];
        __half hh = __float2half(val);
        size_t idx = (size_t)(nb + ng * 8 + i) * KFIN + d * 512 + (k0 + kk);
        g_WcBhi[idx] = hh;
        g_WcBlo[idx] = __float2half(val - __half2float(hh));
    }
}

// ---------------- launch ----------------
extern "C" void kernel_launch(void* const* d_in, const int* in_sizes, int n_in,
                              void* d_out, int out_size)
{
    (void)in_sizes; (void)n_in; (void)out_size;
    const float* x          = (const float*)d_in[0];
    const float* mh_in_w    = (const float*)d_in[1];
    const float* mh_conv_w  = (const float*)d_in[2];
    const float* mh_conv_b  = (const float*)d_in[3];
    const float* mh_dt_bias = (const float*)d_in[4];
    const float* mh_A_log   = (const float*)d_in[5];
    const float* mh_D       = (const float*)d_in[6];
    const float* mh_norm_w  = (const float*)d_in[7];
    const float* mh_out_w   = (const float*)d_in[8];
    const float* mv_in_w    = (const float*)d_in[9];
    const float* mv_conv_w  = (const float*)d_in[10];
    const float* mv_conv_b  = (const float*)d_in[11];
    const float* mv_dt_bias = (const float*)d_in[12];
    const float* mv_A_log   = (const float*)d_in[13];
    const float* mv_D       = (const float*)d_in[14];
    const float* mv_norm_w  = (const float*)d_in[15];
    const float* mv_out_w   = (const float*)d_in[16];
    const float* fc_w       = (const float*)d_in[17];
    const float* fc_b       = (const float*)d_in[18];
    float* out = (float*)d_out;

    float *Zh, *Zv;
    __half *XBCh, *XBCv, *Xhi, *Xlo, *Whhi, *Whlo, *Wvhi, *Wvlo, *Y, *WcBhi, *WcBlo;
    cudaGetSymbolAddress((void**)&Zh,   g_Zh);
    cudaGetSymbolAddress((void**)&Zv,   g_Zv);
    cudaGetSymbolAddress((void**)&XBCh, g_XBCh);
    cudaGetSymbolAddress((void**)&XBCv, g_XBCv);
    cudaGetSymbolAddress((void**)&Xhi,  g_Xhi);
    cudaGetSymbolAddress((void**)&Xlo,  g_Xlo);
    cudaGetSymbolAddress((void**)&Whhi, g_Whhi);
    cudaGetSymbolAddress((void**)&Whlo, g_Whlo);
    cudaGetSymbolAddress((void**)&Wvhi, g_Wvhi);
    cudaGetSymbolAddress((void**)&Wvlo, g_Wvlo);
    cudaGetSymbolAddress((void**)&Y,    g_Y);
    cudaGetSymbolAddress((void**)&WcBhi, g_WcBhi);
    cudaGetSymbolAddress((void**)&WcBlo, g_WcBlo);

    cudaFuncSetAttribute(gemm_mma, cudaFuncAttributeMaxDynamicSharedMemorySize, GSMEM);
    cudaFuncSetAttribute(ssd_kernel, cudaFuncAttributeMaxDynamicSharedMemorySize, SSD_SMEM);

    cvt_x_kernel<<<NTOK * D_MODEL / 4 / 256, 256>>>(x);
    prep_w_kernel<<<dim3((NPAD1 * D_MODEL + 255) / 256, 2), 256>>>(mh_in_w, mv_in_w);
    wcomb_kernel<<<dim3(2, 8, 8), 256>>>(mh_out_w, mv_out_w, fc_w);

    // in-proj: 1-term fp16 (dt tile n0=1152 gets 3-term; xBC tiles written fp16)
    gemm_mma<<<dim3(NTOK / BMg, NPAD1 / BNg, 2), 256, GSMEM>>>(
        Xhi, Xlo, Whhi, Whlo, Wvhi, Wvlo, Zh, Zv, XBCh, XBCv,
        D_MODEL, NPAD1, nullptr, 1152, 1);

    ssd_kernel<<<2 * NSEQ, 512, SSD_SMEM>>>(
        mh_conv_w, mh_conv_b, mh_dt_bias, mh_A_log, mh_D, mh_norm_w,
        mv_conv_w, mv_conv_b, mv_dt_bias, mv_A_log, mv_D, mv_norm_w);

    // final output GEMM: 2-term
    gemm_mma<<<dim3(NTOK / BMg, D_MODEL / BNg, 1), 256, GSMEM>>>(
        Y, Y, WcBhi, WcBlo, WcBhi, WcBlo, out, out, nullptr, nullptr,
        KFIN, D_MODEL, fc_b, -1, 2);
}

// round 13
// speedup vs baseline: 1.9992x; 1.1064x over previous
#include <cuda_runtime.h>
#include <cuda_bf16.h>
#include <cuda_fp16.h>
#include <math.h>
#include <stdint.h>

#define D_MODEL   256
#define D_INNER   512
#define CONV_CH   640
#define D_IN_PROJ 1160
#define SEQ       64
#define NSEQ      512
#define NTOK      32768
#define KFIN      1024
#define NIN       1152     // in-proj real columns (z 512 + xBC 640)

// ---------------- scratch ------------------------------------------------------
__device__ __half g_Z16h[(size_t)NTOK * D_INNER];
__device__ __half g_Z16v[(size_t)NTOK * D_INNER];
__device__ float  g_dth [(size_t)NTOK * 8];
__device__ float  g_dtv [(size_t)NTOK * 8];
__device__ __half g_XBCh[(size_t)NTOK * CONV_CH];
__device__ __half g_XBCv[(size_t)NTOK * CONV_CH];
__device__ __half g_Xhi [(size_t)NTOK * D_MODEL];
__device__ __half g_Whhi[(size_t)NIN * D_MODEL];
__device__ __half g_Wvhi[(size_t)NIN * D_MODEL];
__device__ __half g_Y   [(size_t)NTOK * KFIN];
__device__ __half g_WcBhi[(size_t)D_MODEL * KFIN];
__device__ __half g_WcBlo[(size_t)D_MODEL * KFIN];

extern __shared__ char dynsm[];

// ---------------- helpers ------------------------------------------------------
__device__ __forceinline__ uint32_t smem_u32(const void* p) {
    uint32_t a;
    asm("{ .reg .u64 t; cvta.to.shared.u64 t, %1; cvt.u32.u64 %0, t; }" : "=r"(a) : "l"(p));
    return a;
}
__device__ __forceinline__ uint32_t sw64(uint32_t off) {
    return off ^ ((off >> 3) & 0x30);
}
#define CP16(dst, src) \
    asm volatile("cp.async.cg.shared.global [%0], [%1], 16;" :: "r"(dst), "l"(src))
#define CP_COMMIT() asm volatile("cp.async.commit_group;" ::: "memory")
#define CP_WAIT(n)  asm volatile("cp.async.wait_group %0;" :: "n"(n) : "memory")

__device__ __forceinline__ void ldm4(uint32_t* r, uint32_t addr) {
    asm volatile("ldmatrix.sync.aligned.m8n8.x4.shared.b16 {%0,%1,%2,%3}, [%4];"
        : "=r"(r[0]), "=r"(r[1]), "=r"(r[2]), "=r"(r[3]) : "r"(addr));
}
__device__ __forceinline__ void mma16816(float* d, const uint32_t* a, uint32_t b0, uint32_t b1) {
    asm volatile("mma.sync.aligned.m16n8k16.row.col.f32.f16.f16.f32 "
        "{%0,%1,%2,%3}, {%4,%5,%6,%7}, {%8,%9}, {%0,%1,%2,%3};"
        : "+f"(d[0]), "+f"(d[1]), "+f"(d[2]), "+f"(d[3])
        : "r"(a[0]), "r"(a[1]), "r"(a[2]), "r"(a[3]), "r"(b0), "r"(b1));
}

// ---------------- conversion kernels -------------------------------------------
__global__ void cvt_x_kernel(const float* __restrict__ in) {
    size_t i = (size_t)blockIdx.x * 256 + threadIdx.x;
    float4 v = ((const float4*)in)[i];
    __half2 hi01 = __floats2half2_rn(v.x, v.y);
    __half2 hi23 = __floats2half2_rn(v.z, v.w);
    ((__half2*)g_Xhi)[2 * i]     = hi01;
    ((__half2*)g_Xhi)[2 * i + 1] = hi23;
}

__global__ void prep_w_kernel(const float* __restrict__ wh, const float* __restrict__ wv) {
    int i = blockIdx.x * 256 + threadIdx.x;
    if (i < NIN * D_MODEL) {
        g_Whhi[i] = __float2half(wh[i]);
        g_Wvhi[i] = __float2half(wv[i]);
    }
}

// ---------------- dt kernel: exact fp32 dt = x @ Wdt^T --------------------------
// Wdt = in_w rows 1152..1159 ([8][256]); both dirs in one pass.
__global__ void __launch_bounds__(256) dt_kernel(
    const float* __restrict__ x,
    const float* __restrict__ whd, const float* __restrict__ wvd)
{
    __shared__ float xs[32][260];
    __shared__ float wh[8][260];
    __shared__ float wv[8][260];
    const int tid = threadIdx.x;
    const int row0 = blockIdx.x * 32;
    for (int i = tid; i < 8 * 64; i += 256) {
        int h = i >> 6, c4 = (i & 63) * 4;
        *(float4*)&wh[h][c4] = *(const float4*)&whd[h * 256 + c4];
        *(float4*)&wv[h][c4] = *(const float4*)&wvd[h * 256 + c4];
    }
    for (int i = tid; i < 32 * 64; i += 256) {
        int r = i >> 6, c4 = (i & 63) * 4;
        *(float4*)&xs[r][c4] = *(const float4*)&x[(size_t)(row0 + r) * 256 + c4];
    }
    __syncthreads();
    const int r = tid >> 3, h = tid & 7;
    float ah = 0.f, av = 0.f;
#pragma unroll 8
    for (int k = 0; k < 256; k += 4) {
        float4 xv = *(float4*)&xs[r][k];
        float4 wa = *(float4*)&wh[h][k];
        float4 wb = *(float4*)&wv[h][k];
        ah = fmaf(xv.x, wa.x, ah); ah = fmaf(xv.y, wa.y, ah);
        ah = fmaf(xv.z, wa.z, ah); ah = fmaf(xv.w, wa.w, ah);
        av = fmaf(xv.x, wb.x, av); av = fmaf(xv.y, wb.y, av);
        av = fmaf(xv.z, wb.z, av); av = fmaf(xv.w, wb.w, av);
    }
    g_dth[(size_t)(row0 + r) * 8 + h] = ah;
    g_dtv[(size_t)(row0 + r) * 8 + h] = av;
}

// ---------------- mma.sync fp16 GEMM --------------------------------------------
// mode==1 (in-proj): C = A*Bhi, output fp16 -> Z16 (n0<512) / XBC (n0>=512)
// mode==0 (final)  : C = A*Bhi + A*Blo, output fp32 + bias
#define BMg 128
#define BNg 128
#define TILE_Bg  8192
#define STAGE_Bg 32768
#define GSMEM    (3 * STAGE_Bg)

__global__ void __launch_bounds__(256, 2) gemm_mma(
    const __half* __restrict__ A,
    const __half* __restrict__ B0hi, const __half* __restrict__ B0lo,
    const __half* __restrict__ B1hi, const __half* __restrict__ B1lo,
    float* __restrict__ C,
    __half* __restrict__ Z0, __half* __restrict__ X0,
    __half* __restrict__ Z1, __half* __restrict__ X1,
    int K, int ldc, const float* __restrict__ bias, int mode)
{
    const uint32_t smb = smem_u32(dynsm);
    const int tid = threadIdx.x, lane = tid & 31, wid = tid >> 5;
    const int m0 = blockIdx.x * BMg, n0 = blockIdx.y * BNg;
    const int wm = (wid & 1) * 64, wn = 32 * (wid >> 1);
    const int nk = K >> 5;
    const bool use_blo = (mode == 0);

    const __half* Bhi = blockIdx.z ? B1hi : B0hi;
    const __half* Blo = blockIdx.z ? B1lo : B0lo;
    __half* Z16 = blockIdx.z ? Z1 : Z0;
    __half* XB  = blockIdx.z ? X1 : X0;

    uint32_t arow[4], brow[2];
#pragma unroll
    for (int mt = 0; mt < 4; mt++)
        arow[mt] = (uint32_t)(wm + mt * 16 + (lane & 15)) * 64 + (lane >> 4) * 16;
#pragma unroll
    for (int nb = 0; nb < 2; nb++)
        brow[nb] = (uint32_t)(wn + nb * 16 + (lane & 15)) * 64 + (lane >> 4) * 16;

    float acc[4][4][4];
#pragma unroll
    for (int a = 0; a < 4; a++)
#pragma unroll
        for (int b = 0; b < 4; b++)
#pragma unroll
            for (int c = 0; c < 4; c++) acc[a][b][c] = 0.f;

    const int lrow = tid & 127, hf = tid >> 7;
    const uint32_t rb = (uint32_t)lrow * 64 + hf * 32;

    auto load_stage = [&](int s, int c) {
        const int koff = c * 32 + hf * 16;
        const uint32_t base = smb + s * STAGE_Bg;
        const __half* pA   = A   + (size_t)(m0 + lrow) * K + koff;
        const __half* pBhi = Bhi + (size_t)(n0 + lrow) * K + koff;
#pragma unroll
        for (int ch = 0; ch < 2; ch++) {
            uint32_t d = sw64(rb + ch * 16);
            CP16(base + d, pA + ch * 8);
            CP16(base + 2 * TILE_Bg + d, pBhi + ch * 8);
        }
        if (use_blo) {
            const __half* pBlo = Blo + (size_t)(n0 + lrow) * K + koff;
#pragma unroll
            for (int ch = 0; ch < 2; ch++)
                CP16(base + 3 * TILE_Bg + sw64(rb + ch * 16), pBlo + ch * 8);
        }
        CP_COMMIT();
    };

    load_stage(0, 0);
    load_stage(1, 1);

    for (int c = 0; c < nk; c++) {
        if (c + 1 < nk) CP_WAIT(1); else CP_WAIT(0);
        __syncthreads();
        if (c + 2 < nk) load_stage((c + 2) % 3, c + 2);

        const uint32_t base = smb + (c % 3) * STAGE_Bg;
        const uint32_t aB = base;
        const uint32_t bHiB = base + 2 * TILE_Bg, bLoB = base + 3 * TILE_Bg;
#pragma unroll
        for (int ks = 0; ks < 2; ks++) {
            uint32_t af[4][4], bhi[2][4], blo[2][4];
#pragma unroll
            for (int mt = 0; mt < 4; mt++)
                ldm4(af[mt], aB + sw64(arow[mt] + ks * 32));
#pragma unroll
            for (int nb = 0; nb < 2; nb++)
                ldm4(bhi[nb], bHiB + sw64(brow[nb] + ks * 32));
            if (use_blo) {
#pragma unroll
                for (int nb = 0; nb < 2; nb++)
                    ldm4(blo[nb], bLoB + sw64(brow[nb] + ks * 32));
            }
#pragma unroll
            for (int mt = 0; mt < 4; mt++)
#pragma unroll
                for (int nb = 0; nb < 2; nb++) {
                    mma16816(acc[mt][nb * 2],     af[mt], bhi[nb][0], bhi[nb][2]);
                    mma16816(acc[mt][nb * 2 + 1], af[mt], bhi[nb][1], bhi[nb][3]);
                }
            if (use_blo) {
#pragma unroll
                for (int mt = 0; mt < 4; mt++)
#pragma unroll
                    for (int nb = 0; nb < 2; nb++) {
                        mma16816(acc[mt][nb * 2],     af[mt], blo[nb][0], blo[nb][2]);
                        mma16816(acc[mt][nb * 2 + 1], af[mt], blo[nb][1], blo[nb][3]);
                    }
            }
        }
    }

#pragma unroll
    for (int mt = 0; mt < 4; mt++) {
        int row = m0 + wm + mt * 16 + (lane >> 2);
#pragma unroll
        for (int nt = 0; nt < 4; nt++) {
            int col = n0 + wn + nt * 8 + (lane & 3) * 2;
            float2 v0 = make_float2(acc[mt][nt][0], acc[mt][nt][1]);
            float2 v1 = make_float2(acc[mt][nt][2], acc[mt][nt][3]);
            if (mode == 1) {
                if (col < 512) {
                    *(__half2*)&Z16[(size_t)row * 512 + col]       = __floats2half2_rn(v0.x, v0.y);
                    *(__half2*)&Z16[(size_t)(row + 8) * 512 + col] = __floats2half2_rn(v1.x, v1.y);
                } else {
                    int xc = col - 512;
                    *(__half2*)&XB[(size_t)row * 640 + xc]       = __floats2half2_rn(v0.x, v0.y);
                    *(__half2*)&XB[(size_t)(row + 8) * 640 + xc] = __floats2half2_rn(v1.x, v1.y);
                }
            } else {
                float b0 = bias[col], b1 = bias[col + 1];
                v0.x += b0; v0.y += b1; v1.x += b0; v1.y += b1;
                *(float2*)&C[(size_t)row * ldc + col] = v0;
                *(float2*)&C[(size_t)(row + 8) * ldc + col] = v1;
            }
        }
    }
}

// ---------------- SSD kernel ----------------------------------------------------
#define RAW_PITCH 1296
#define XDT_PITCH 144
#define G_PITCH   68
#define GSM_PITCH 520

#define RAW_OFF   0
#define GSM_OFF   0
#define XDT_OFF   86832
#define BM_OFF    160560
#define CM_OFF    169776
#define G_OFF     178992
#define GMH_OFF   196400
#define GML_OFF   205616
#define L_OFF     214832
#define DTS_OFF   216880
#define DDT_OFF   218928
#define NW_OFF    220976
#define SSD_SMEM  223040

__global__ void __launch_bounds__(512, 1) ssd_kernel(
    const float* __restrict__ cwh, const float* __restrict__ cbh,
    const float* __restrict__ dtbh, const float* __restrict__ Alh,
    const float* __restrict__ Dh_, const float* __restrict__ nwh,
    const float* __restrict__ cwv, const float* __restrict__ cbv,
    const float* __restrict__ dtbv, const float* __restrict__ Alv,
    const float* __restrict__ Dv_, const float* __restrict__ nwv)
{
    char* sm = dynsm;
    const uint32_t smb = smem_u32(sm);
    const int tid = threadIdx.x, lane = tid & 31, wid = tid >> 5;
    const int dir = blockIdx.x >> 9;
    const int s   = blockIdx.x & 511;

    const __half* Z16     = dir ? g_Z16v : g_Z16h;
    const float*  DT      = dir ? g_dtv : g_dth;
    const __half* XBC     = dir ? g_XBCv : g_XBCh;
    const float*  conv_w  = dir ? cwv : cwh;
    const float*  conv_b  = dir ? cbv : cbh;
    const float*  dt_bias = dir ? dtbv : dtbh;
    const float*  A_log   = dir ? Alv : Alh;
    const float*  Dv      = dir ? Dv_ : Dh_;
    const float*  norm_w  = dir ? nwv : nwh;
    const int ycol = dir ? 0 : 512;

    int base, stride;
    if (dir) { int b = s >> 6, w = s & 63; base = b * 4096 + w; stride = 64; }
    else     { base = s * 64; stride = 1; }

    __half* XdT = (__half*)(sm + XDT_OFF);
    __half* Bm  = (__half*)(sm + BM_OFF);
    __half* Cm  = (__half*)(sm + CM_OFF);
    float*  G   = (float*)(sm + G_OFF);
    float*  Lc  = (float*)(sm + L_OFF);
    float*  dts = (float*)(sm + DTS_OFF);
    float*  Ddt = (float*)(sm + DDT_OFF);
    float*  nws = (float*)(sm + NW_OFF);
    __half* gsm = (__half*)(sm + GSM_OFF);

    nws[tid] = norm_w[tid];
    ((uint32_t*)sm)[tid] = 0;
    if (tid < 460) ((uint32_t*)sm)[tid + 512] = 0;

#pragma unroll
    for (int j = 0; j < 10; j++) {
        int idx = tid + j * 512;
        int row = idx / 80, c16 = idx % 80;
        uint32_t dst = smb + RAW_OFF + (uint32_t)(row + 3) * RAW_PITCH + c16 * 16;
        const __half* src = XBC + (size_t)(base + row * stride) * 640 + c16 * 8;
        CP16(dst, src);
    }
    CP_COMMIT();

    // dt / cumsum: warp h handles head h
    if (wid < 8) {
        const int h = wid;
        const float Aneg = -__expf(A_log[h]);
        const float dtb = dt_bias[h];
        const float Dh = Dv[h];
        float v0, v1;
        {
            int t = lane;
            float draw = DT[(size_t)(base + t * stride) * 8 + h] + dtb;
            float dt = (draw > 20.f) ? draw : log1pf(__expf(draw));
            dts[h * 64 + t] = dt; Ddt[h * 64 + t] = Dh / dt;
            v0 = dt * Aneg;
        }
        {
            int t = lane + 32;
            float draw = DT[(size_t)(base + t * stride) * 8 + h] + dtb;
            float dt = (draw > 20.f) ? draw : log1pf(__expf(draw));
            dts[h * 64 + t] = dt; Ddt[h * 64 + t] = Dh / dt;
            v1 = dt * Aneg;
        }
        float a = v0;
#pragma unroll
        for (int o = 1; o < 32; o <<= 1) {
            float u = __shfl_up_sync(0xffffffffu, a, o);
            if (lane >= o) a += u;
        }
        float tot = __shfl_sync(0xffffffffu, a, 31);
        float b = v1;
#pragma unroll
        for (int o = 1; o < 32; o <<= 1) {
            float u = __shfl_up_sync(0xffffffffu, b, o);
            if (lane >= o) b += u;
        }
        b += tot;
        Lc[h * 64 + lane] = a;
        Lc[h * 64 + 32 + lane] = b;
    }
    CP_WAIT(0);
    __syncthreads();

    // conv + SiLU
    {
        const int c = tid, hd = c >> 6;
        const float w0 = conv_w[c * 4], w1 = conv_w[c * 4 + 1];
        const float w2 = conv_w[c * 4 + 2], w3 = conv_w[c * 4 + 3];
        const float cb = conv_b[c];
        const bool isbc = (tid < 128);
        const int c2 = 512 + tid;
        float u0 = 0, u1 = 0, u2 = 0, u3 = 0, ub = 0;
        __half* dstBC = (tid < 64) ? (Bm + tid) : (Cm + (tid - 64));
        if (isbc) {
            u0 = conv_w[c2 * 4]; u1 = conv_w[c2 * 4 + 1];
            u2 = conv_w[c2 * 4 + 2]; u3 = conv_w[c2 * 4 + 3];
            ub = conv_b[c2];
        }
        float r0 = 0, r1 = 0, r2 = 0, q0 = 0, q1 = 0, q2 = 0;
        for (int t = 0; t < SEQ; t++) {
            float cur = __half2float(*(__half*)(sm + RAW_OFF + (t + 3) * RAW_PITCH + c * 2));
            float v = fmaf(cur, w3, fmaf(r2, w2, fmaf(r1, w1, fmaf(r0, w0, cb))));
            r0 = r1; r1 = r2; r2 = cur;
            v = v / (1.f + __expf(-v));
            XdT[c * 72 + t] = __float2half(v * dts[hd * 64 + t]);
            if (isbc) {
                float cq = __half2float(*(__half*)(sm + RAW_OFF + (t + 3) * RAW_PITCH + c2 * 2));
                float vq = fmaf(cq, u3, fmaf(q2, u2, fmaf(q1, u1, fmaf(q0, u0, ub))));
                q0 = q1; q1 = q2; q2 = cq;
                vq = vq / (1.f + __expf(-vq));
                dstBC[t * 72] = __float2half(vq);
            }
        }
    }
    __syncthreads();

    // G = C @ B^T (64x64x64)
    const int mi = wid & 3, nj = wid >> 2;
    {
        float acc[2][4];
#pragma unroll
        for (int i = 0; i < 2; i++)
#pragma unroll
            for (int j = 0; j < 4; j++) acc[i][j] = 0.f;
#pragma unroll
        for (int ks = 0; ks < 4; ks++) {
            uint32_t a[4], bq[4];
            ldm4(a,  smb + CM_OFF + (mi * 16 + (lane & 15)) * XDT_PITCH + (lane >> 4) * 16 + ks * 32);
            ldm4(bq, smb + BM_OFF + (nj * 16 + (lane & 15)) * XDT_PITCH + (lane >> 4) * 16 + ks * 32);
            mma16816(acc[0], a, bq[0], bq[2]);
            mma16816(acc[1], a, bq[1], bq[3]);
        }
        const int r = lane >> 2, cc = (lane & 3) * 2;
#pragma unroll
        for (int nt = 0; nt < 2; nt++) {
            int sc = nj * 16 + nt * 8 + cc;
            *(float2*)&G[(mi * 16 + r) * G_PITCH + sc]     = make_float2(acc[nt][0], acc[nt][1]);
            *(float2*)&G[(mi * 16 + r + 8) * G_PITCH + sc] = make_float2(acc[nt][2], acc[nt][3]);
        }
    }
    __syncthreads();

    // per-head masked GEMMs
    for (int h = 0; h < 8; h++) {
        const float* Lh = Lc + h * 64;
        __half* Gmh = (__half*)(sm + GMH_OFF);
        __half* Gml = (__half*)(sm + GML_OFF);
#pragma unroll
        for (int k = 0; k < 8; k++) {
            int idx = tid + k * 512;
            int t = idx >> 6, sc = idx & 63;
            float w = 0.f;
            if (sc <= t) w = __expf(Lh[t] - Lh[sc]);
            float gm = G[t * G_PITCH + sc] * w;
            if (sc == t) gm += Ddt[h * 64 + t];
            __half hi = __float2half(gm);
            Gmh[t * 72 + sc] = hi;
            Gml[t * 72 + sc] = __float2half(gm - __half2float(hi));
        }
        __syncthreads();

        float acc[2][4];
#pragma unroll
        for (int i = 0; i < 2; i++)
#pragma unroll
            for (int j = 0; j < 4; j++) acc[i][j] = 0.f;
#pragma unroll
        for (int ks = 0; ks < 4; ks++) {
            uint32_t ah[4], al[4], bq[4];
            uint32_t ro = (mi * 16 + (lane & 15)) * XDT_PITCH + (lane >> 4) * 16 + ks * 32;
            ldm4(ah, smb + GMH_OFF + ro);
            ldm4(al, smb + GML_OFF + ro);
            ldm4(bq, smb + XDT_OFF + (uint32_t)(h * 64 + nj * 16 + (lane & 15)) * XDT_PITCH
                        + (lane >> 4) * 16 + ks * 32);
            mma16816(acc[0], ah, bq[0], bq[2]);
            mma16816(acc[1], ah, bq[1], bq[3]);
            mma16816(acc[0], al, bq[0], bq[2]);
            mma16816(acc[1], al, bq[1], bq[3]);
        }
        const int r = lane >> 2, cc = (lane & 3) * 2;
#pragma unroll
        for (int nt = 0; nt < 2; nt++)
#pragma unroll
            for (int rr = 0; rr < 2; rr++) {
                int t = mi * 16 + r + rr * 8;
                int p = nj * 16 + nt * 8 + cc;
                float y0 = acc[nt][rr * 2 + 0], y1 = acc[nt][rr * 2 + 1];
                __half2 zv = *(__half2*)&Z16[(size_t)(base + t * stride) * 512 + h * 64 + p];
                float z0 = __half2float(zv.x), z1 = __half2float(zv.y);
                float g0 = y0 * z0 / (1.f + __expf(-z0));
                float g1 = y1 * z1 / (1.f + __expf(-z1));
                *(__half2*)&gsm[t * GSM_PITCH + h * 64 + p] = __floats2half2_rn(g0, g1);
            }
        __syncthreads();
    }

    // RMS norm + output
#pragma unroll
    for (int k = 0; k < 4; k++) {
        int t = wid + k * 16;
        float ss = 0.f;
        float2 gv[8];
#pragma unroll
        for (int j = 0; j < 8; j++) {
            __half2 hv = *(__half2*)&gsm[t * GSM_PITCH + j * 64 + lane * 2];
            float a = __half2float(hv.x), b = __half2float(hv.y);
            gv[j] = make_float2(a, b);
            ss = fmaf(a, a, ss); ss = fmaf(b, b, ss);
        }
#pragma unroll
        for (int o = 16; o; o >>= 1) ss += __shfl_xor_sync(0xffffffffu, ss, o);
        float sinv = rsqrtf(ss * (1.0f / 512.0f) + 1e-5f);
        size_t orow = (size_t)(base + t * stride) * KFIN + ycol;
#pragma unroll
        for (int j = 0; j < 8; j++) {
            int c = j * 64 + lane * 2;
            float a = gv[j].x * sinv * nws[c];
            float b = gv[j].y * sinv * nws[c + 1];
            *(__half2*)&g_Y[orow + c] = __floats2half2_rn(a, b);
        }
    }
}

// ---------------- fold fc_w into out_w -----------------------------------------
__global__ void __launch_bounds__(256) wcomb_kernel(
    const float* __restrict__ mh_out_w, const float* __restrict__ mv_out_w,
    const float* __restrict__ fc_w)
{
    const int d  = blockIdx.x;
    const int k0 = blockIdx.y * 64;
    const int nb = blockIdx.z * 32;
    const float* ow = d ? mh_out_w : mv_out_w;
    const int fo = d ? 512 : 0;
    __shared__ float ows[64][65];
    __shared__ float fs[32][65];
    const int kk = threadIdx.x & 63;
    const int ng = threadIdx.x >> 6;
    float acc[8];
#pragma unroll
    for (int i = 0; i < 8; i++) acc[i] = 0.f;

    for (int jo = 0; jo < 256; jo += 64) {
        for (int idx = threadIdx.x; idx < 64 * 64; idx += 256) {
            int j = idx >> 6, c = idx & 63;
            ows[j][c] = ow[(size_t)(jo + j) * 512 + k0 + c];
        }
        for (int idx = threadIdx.x; idx < 32 * 64; idx += 256) {
            int n = idx >> 6, jj = idx & 63;
            fs[n][jj] = fc_w[(size_t)(nb + n) * 1024 + fo + jo + jj] +
                        fc_w[(size_t)(nb + n) * 1024 + fo + 256 + jo + jj];
        }
        __syncthreads();
#pragma unroll 4
        for (int j = 0; j < 64; j++) {
            float o = ows[j][kk];
#pragma unroll
            for (int i = 0; i < 8; i++)
                acc[i] = fmaf(o, fs[ng * 8 + i][j], acc[i]);
        }
        __syncthreads();
    }
#pragma unroll
    for (int i = 0; i < 8; i++) {
        float val = acc[i];
        __half hh = __float2half(val);
        size_t idx = (size_t)(nb + ng * 8 + i) * KFIN + d * 512 + (k0 + kk);
        g_WcBhi[idx] = hh;
        g_WcBlo[idx] = __float2half(val - __half2float(hh));
    }
}

// ---------------- launch ----------------
extern "C" void kernel_launch(void* const* d_in, const int* in_sizes, int n_in,
                              void* d_out, int out_size)
{
    (void)in_sizes; (void)n_in; (void)out_size;
    const float* x          = (const float*)d_in[0];
    const float* mh_in_w    = (const float*)d_in[1];
    const float* mh_conv_w  = (const float*)d_in[2];
    const float* mh_conv_b  = (const float*)d_in[3];
    const float* mh_dt_bias = (const float*)d_in[4];
    const float* mh_A_log   = (const float*)d_in[5];
    const float* mh_D       = (const float*)d_in[6];
    const float* mh_norm_w  = (const float*)d_in[7];
    const float* mh_out_w   = (const float*)d_in[8];
    const float* mv_in_w    = (const float*)d_in[9];
    const float* mv_conv_w  = (const float*)d_in[10];
    const float* mv_conv_b  = (const float*)d_in[11];
    const float* mv_dt_bias = (const float*)d_in[12];
    const float* mv_A_log   = (const float*)d_in[13];
    const float* mv_D       = (const float*)d_in[14];
    const float* mv_norm_w  = (const float*)d_in[15];
    const float* mv_out_w   = (const float*)d_in[16];
    const float* fc_w       = (const float*)d_in[17];
    const float* fc_b       = (const float*)d_in[18];
    float* out = (float*)d_out;

    __half *Z16h, *Z16v, *XBCh, *XBCv, *Xhi, *Whhi, *Wvhi, *Y, *WcBhi, *WcBlo;
    cudaGetSymbolAddress((void**)&Z16h, g_Z16h);
    cudaGetSymbolAddress((void**)&Z16v, g_Z16v);
    cudaGetSymbolAddress((void**)&XBCh, g_XBCh);
    cudaGetSymbolAddress((void**)&XBCv, g_XBCv);
    cudaGetSymbolAddress((void**)&Xhi,  g_Xhi);
    cudaGetSymbolAddress((void**)&Whhi, g_Whhi);
    cudaGetSymbolAddress((void**)&Wvhi, g_Wvhi);
    cudaGetSymbolAddress((void**)&Y,    g_Y);
    cudaGetSymbolAddress((void**)&WcBhi, g_WcBhi);
    cudaGetSymbolAddress((void**)&WcBlo, g_WcBlo);

    cudaFuncSetAttribute(gemm_mma, cudaFuncAttributeMaxDynamicSharedMemorySize, GSMEM);
    cudaFuncSetAttribute(ssd_kernel, cudaFuncAttributeMaxDynamicSharedMemorySize, SSD_SMEM);

    cvt_x_kernel<<<NTOK * D_MODEL / 4 / 256, 256>>>(x);
    prep_w_kernel<<<(NIN * D_MODEL + 255) / 256, 256>>>(mh_in_w, mv_in_w);
    wcomb_kernel<<<dim3(2, 8, 8), 256>>>(mh_out_w, mv_out_w, fc_w);
    dt_kernel<<<NTOK / 32, 256>>>(x, mh_in_w + 1152 * 256, mv_in_w + 1152 * 256);

    // in-proj: 1-term fp16, fp16 outputs (z + xBC)
    gemm_mma<<<dim3(NTOK / BMg, NIN / BNg, 2), 256, GSMEM>>>(
        Xhi, Whhi, Whhi, Wvhi, Wvhi, nullptr,
        Z16h, XBCh, Z16v, XBCv, D_MODEL, 0, nullptr, 1);

    ssd_kernel<<<2 * NSEQ, 512, SSD_SMEM>>>(
        mh_conv_w, mh_conv_b, mh_dt_bias, mh_A_log, mh_D, mh_norm_w,
        mv_conv_w, mv_conv_b, mv_dt_bias, mv_A_log, mv_D, mv_norm_w);

    // final output GEMM: 2-term, fp32 out + bias
    gemm_mma<<<dim3(NTOK / BMg, D_MODEL / BNg, 1), 256, GSMEM>>>(
        Y, WcBhi, WcBlo, WcBhi, WcBlo, out,
        nullptr, nullptr, nullptr, nullptr, KFIN, D_MODEL, fc_b, 0);
}

// round 14
// speedup vs baseline: 2.4654x; 1.2332x over previous
#include <cuda_runtime.h>
#include <cuda_bf16.h>
#include <cuda_fp16.h>
#include <math.h>
#include <stdint.h>

#define D_MODEL   256
#define D_INNER   512
#define CONV_CH   640
#define SEQ       64
#define NSEQ      512
#define NTOK      32768
#define KFIN      1024
#define NIN       1152

// ---------------- scratch ------------------------------------------------------
__device__ __half g_Z16h[(size_t)NTOK * D_INNER];
__device__ __half g_Z16v[(size_t)NTOK * D_INNER];
__device__ float  g_dth [(size_t)NTOK * 8];
__device__ float  g_dtv [(size_t)NTOK * 8];
__device__ __half g_XBCh[(size_t)NTOK * CONV_CH];
__device__ __half g_XBCv[(size_t)NTOK * CONV_CH];
__device__ __half g_Xhi [(size_t)NTOK * D_MODEL];
__device__ __half g_Whhi[(size_t)NIN * D_MODEL];
__device__ __half g_Wvhi[(size_t)NIN * D_MODEL];
__device__ __half g_Y   [(size_t)NTOK * KFIN];
__device__ __half g_WcBhi[(size_t)D_MODEL * KFIN];
__device__ __half g_WcBlo[(size_t)D_MODEL * KFIN];

extern __shared__ char dynsm[];

// ---------------- helpers ------------------------------------------------------
__device__ __forceinline__ uint32_t smem_u32(const void* p) {
    uint32_t a;
    asm("{ .reg .u64 t; cvta.to.shared.u64 t, %1; cvt.u32.u64 %0, t; }" : "=r"(a) : "l"(p));
    return a;
}
__device__ __forceinline__ uint32_t swz128(uint32_t off) {
    return off ^ ((off >> 3) & 0x70);
}
#define CP16(dst, src) \
    asm volatile("cp.async.cg.shared.global [%0], [%1], 16;" :: "r"(dst), "l"(src))
#define CP_COMMIT() asm volatile("cp.async.commit_group;" ::: "memory")
#define CP_WAIT(n)  asm volatile("cp.async.wait_group %0;" :: "n"(n) : "memory")

__device__ __forceinline__ void ldm4(uint32_t* r, uint32_t addr) {
    asm volatile("ldmatrix.sync.aligned.m8n8.x4.shared.b16 {%0,%1,%2,%3}, [%4];"
        : "=r"(r[0]), "=r"(r[1]), "=r"(r[2]), "=r"(r[3]) : "r"(addr));
}
__device__ __forceinline__ void mma16816(float* d, const uint32_t* a, uint32_t b0, uint32_t b1) {
    asm volatile("mma.sync.aligned.m16n8k16.row.col.f32.f16.f16.f32 "
        "{%0,%1,%2,%3}, {%4,%5,%6,%7}, {%8,%9}, {%0,%1,%2,%3};"
        : "+f"(d[0]), "+f"(d[1]), "+f"(d[2]), "+f"(d[3])
        : "r"(a[0]), "r"(a[1]), "r"(a[2]), "r"(a[3]), "r"(b0), "r"(b1));
}

// ---------------- conversion kernels -------------------------------------------
__global__ void cvt_x_kernel(const float* __restrict__ in) {
    size_t i = (size_t)blockIdx.x * 256 + threadIdx.x;
    float4 v = ((const float4*)in)[i];
    ((__half2*)g_Xhi)[2 * i]     = __floats2half2_rn(v.x, v.y);
    ((__half2*)g_Xhi)[2 * i + 1] = __floats2half2_rn(v.z, v.w);
}

__global__ void prep_w_kernel(const float* __restrict__ wh, const float* __restrict__ wv) {
    int i = blockIdx.x * 256 + threadIdx.x;
    if (i < NIN * D_MODEL) {
        g_Whhi[i] = __float2half(wh[i]);
        g_Wvhi[i] = __float2half(wv[i]);
    }
}

// ---------------- dt kernel: exact fp32 dt = x @ Wdt^T --------------------------
__global__ void __launch_bounds__(256) dt_kernel(
    const float* __restrict__ x,
    const float* __restrict__ whd, const float* __restrict__ wvd)
{
    __shared__ float xs[32][260];
    __shared__ float wh[8][260];
    __shared__ float wv[8][260];
    const int tid = threadIdx.x;
    const int row0 = blockIdx.x * 32;
    for (int i = tid; i < 8 * 64; i += 256) {
        int h = i >> 6, c4 = (i & 63) * 4;
        *(float4*)&wh[h][c4] = *(const float4*)&whd[h * 256 + c4];
        *(float4*)&wv[h][c4] = *(const float4*)&wvd[h * 256 + c4];
    }
    for (int i = tid; i < 32 * 64; i += 256) {
        int r = i >> 6, c4 = (i & 63) * 4;
        *(float4*)&xs[r][c4] = *(const float4*)&x[(size_t)(row0 + r) * 256 + c4];
    }
    __syncthreads();
    const int r = tid >> 3, h = tid & 7;
    float ah = 0.f, av = 0.f;
#pragma unroll 8
    for (int k = 0; k < 256; k += 4) {
        float4 xv = *(float4*)&xs[r][k];
        float4 wa = *(float4*)&wh[h][k];
        float4 wb = *(float4*)&wv[h][k];
        ah = fmaf(xv.x, wa.x, ah); ah = fmaf(xv.y, wa.y, ah);
        ah = fmaf(xv.z, wa.z, ah); ah = fmaf(xv.w, wa.w, ah);
        av = fmaf(xv.x, wb.x, av); av = fmaf(xv.y, wb.y, av);
        av = fmaf(xv.z, wb.z, av); av = fmaf(xv.w, wb.w, av);
    }
    g_dth[(size_t)(row0 + r) * 8 + h] = ah;
    g_dtv[(size_t)(row0 + r) * 8 + h] = av;
}

// ---------------- mma.sync fp16 GEMM, BK=64 -------------------------------------
// mode==1 (in-proj): C = A*Bhi, fp16 out, 3-stage (32 KB/stage)
// mode==0 (final)  : C = A*Bhi + A*Blo, fp32 out + bias, 2-stage (48 KB/stage)
#define BMg 128
#define BNg 128
#define TILE64_B 16384           // 128 rows x 128 B
#define GSMEM    98304

__global__ void __launch_bounds__(256, 2) gemm_mma(
    const __half* __restrict__ A,
    const __half* __restrict__ B0hi, const __half* __restrict__ B0lo,
    const __half* __restrict__ B1hi, const __half* __restrict__ B1lo,
    float* __restrict__ C,
    __half* __restrict__ Z0, __half* __restrict__ X0,
    __half* __restrict__ Z1, __half* __restrict__ X1,
    int K, int ldc, const float* __restrict__ bias, int mode)
{
    const uint32_t smb = smem_u32(dynsm);
    const int tid = threadIdx.x, lane = tid & 31, wid = tid >> 5;
    const int m0 = blockIdx.x * BMg, n0 = blockIdx.y * BNg;
    const int wm = (wid & 1) * 64, wn = 32 * (wid >> 1);
    const int nk = K >> 6;
    const bool use_blo = (mode == 0);
    const uint32_t stageB = use_blo ? 49152 : 32768;

    const __half* Bhi = blockIdx.z ? B1hi : B0hi;
    const __half* Blo = blockIdx.z ? B1lo : B0lo;
    __half* Z16 = blockIdx.z ? Z1 : Z0;
    __half* XB  = blockIdx.z ? X1 : X0;

    uint32_t arow[4], brow[2];
#pragma unroll
    for (int mt = 0; mt < 4; mt++)
        arow[mt] = (uint32_t)(wm + mt * 16 + (lane & 15)) * 128 + (lane >> 4) * 16;
#pragma unroll
    for (int nb = 0; nb < 2; nb++)
        brow[nb] = (uint32_t)(wn + nb * 16 + (lane & 15)) * 128 + (lane >> 4) * 16;

    float acc[4][4][4];
#pragma unroll
    for (int a = 0; a < 4; a++)
#pragma unroll
        for (int b = 0; b < 4; b++)
#pragma unroll
            for (int c = 0; c < 4; c++) acc[a][b][c] = 0.f;

    const int lrow = tid >> 1, cq = (tid & 1) * 4;

    auto load_stage = [&](int s, int c) {
        const int koff = c * 64;
        const uint32_t base = smb + s * stageB;
        const __half* pA   = A   + (size_t)(m0 + lrow) * K + koff;
        const __half* pBhi = Bhi + (size_t)(n0 + lrow) * K + koff;
        const uint32_t rb = (uint32_t)lrow * 128;
#pragma unroll
        for (int ch = 0; ch < 4; ch++) {
            uint32_t d = swz128(rb + (cq + ch) * 16);
            CP16(base + d, pA + (cq + ch) * 8);
            CP16(base + TILE64_B + d, pBhi + (cq + ch) * 8);
        }
        if (use_blo) {
            const __half* pBlo = Blo + (size_t)(n0 + lrow) * K + koff;
#pragma unroll
            for (int ch = 0; ch < 4; ch++)
                CP16(base + 2 * TILE64_B + swz128(rb + (cq + ch) * 16), pBlo + (cq + ch) * 8);
        }
        CP_COMMIT();
    };

    if (!use_blo) { load_stage(0, 0); load_stage(1, 1); }
    else          { load_stage(0, 0); }

    for (int c = 0; c < nk; c++) {
        int sidx;
        if (!use_blo) {
            if (c + 1 < nk) CP_WAIT(1); else CP_WAIT(0);
            __syncthreads();
            if (c + 2 < nk) load_stage((c + 2) % 3, c + 2);
            sidx = c % 3;
        } else {
            CP_WAIT(0);
            __syncthreads();
            if (c + 1 < nk) load_stage((c + 1) & 1, c + 1);
            sidx = c & 1;
        }

        const uint32_t base = smb + sidx * stageB;
        const uint32_t aB = base, bHiB = base + TILE64_B, bLoB = base + 2 * TILE64_B;
#pragma unroll
        for (int ks = 0; ks < 4; ks++) {
            uint32_t af[4][4], bhi[2][4], blo[2][4];
#pragma unroll
            for (int mt = 0; mt < 4; mt++)
                ldm4(af[mt], aB + swz128(arow[mt] + ks * 32));
#pragma unroll
            for (int nb = 0; nb < 2; nb++)
                ldm4(bhi[nb], bHiB + swz128(brow[nb] + ks * 32));
            if (use_blo) {
#pragma unroll
                for (int nb = 0; nb < 2; nb++)
                    ldm4(blo[nb], bLoB + swz128(brow[nb] + ks * 32));
            }
#pragma unroll
            for (int mt = 0; mt < 4; mt++)
#pragma unroll
                for (int nb = 0; nb < 2; nb++) {
                    mma16816(acc[mt][nb * 2],     af[mt], bhi[nb][0], bhi[nb][2]);
                    mma16816(acc[mt][nb * 2 + 1], af[mt], bhi[nb][1], bhi[nb][3]);
                }
            if (use_blo) {
#pragma unroll
                for (int mt = 0; mt < 4; mt++)
#pragma unroll
                    for (int nb = 0; nb < 2; nb++) {
                        mma16816(acc[mt][nb * 2],     af[mt], blo[nb][0], blo[nb][2]);
                        mma16816(acc[mt][nb * 2 + 1], af[mt], blo[nb][1], blo[nb][3]);
                    }
            }
        }
    }

#pragma unroll
    for (int mt = 0; mt < 4; mt++) {
        int row = m0 + wm + mt * 16 + (lane >> 2);
#pragma unroll
        for (int nt = 0; nt < 4; nt++) {
            int col = n0 + wn + nt * 8 + (lane & 3) * 2;
            float2 v0 = make_float2(acc[mt][nt][0], acc[mt][nt][1]);
            float2 v1 = make_float2(acc[mt][nt][2], acc[mt][nt][3]);
            if (mode == 1) {
                if (col < 512) {
                    *(__half2*)&Z16[(size_t)row * 512 + col]       = __floats2half2_rn(v0.x, v0.y);
                    *(__half2*)&Z16[(size_t)(row + 8) * 512 + col] = __floats2half2_rn(v1.x, v1.y);
                } else {
                    int xc = col - 512;
                    *(__half2*)&XB[(size_t)row * 640 + xc]       = __floats2half2_rn(v0.x, v0.y);
                    *(__half2*)&XB[(size_t)(row + 8) * 640 + xc] = __floats2half2_rn(v1.x, v1.y);
                }
            } else {
                float b0 = bias[col], b1 = bias[col + 1];
                v0.x += b0; v0.y += b1; v1.x += b0; v1.y += b1;
                *(float2*)&C[(size_t)row * ldc + col] = v0;
                *(float2*)&C[(size_t)(row + 8) * ldc + col] = v1;
            }
        }
    }
}

// ---------------- SSD kernel ----------------------------------------------------
#define RAW_PITCH 1296
#define XDT_PITCH 144
#define G_PITCH   68
#define GSM_PITCH 520

#define GSM_OFF   0
#define G_OFF     66560     // inside RAW union (RAW dead after conv)
#define XDT_OFF   86832
#define BM_OFF    160560
#define CM_OFF    169776
#define GMH_OFF   178992
#define GML_OFF   188208
#define ZBUF_OFF  197424    // 2 x 8192
#define L_OFF     213808
#define DTS_OFF   215856
#define DDT_OFF   217904
#define NW_OFF    219952
#define SSD_SMEM  222000

__global__ void __launch_bounds__(512, 1) ssd_kernel(
    const float* __restrict__ cwh, const float* __restrict__ cbh,
    const float* __restrict__ dtbh, const float* __restrict__ Alh,
    const float* __restrict__ Dh_, const float* __restrict__ nwh,
    const float* __restrict__ cwv, const float* __restrict__ cbv,
    const float* __restrict__ dtbv, const float* __restrict__ Alv,
    const float* __restrict__ Dv_, const float* __restrict__ nwv)
{
    char* sm = dynsm;
    const uint32_t smb = smem_u32(sm);
    const int tid = threadIdx.x, lane = tid & 31, wid = tid >> 5;
    const int dir = blockIdx.x >> 9;
    const int s   = blockIdx.x & 511;

    const __half* Z16     = dir ? g_Z16v : g_Z16h;
    const float*  DT      = dir ? g_dtv : g_dth;
    const __half* XBC     = dir ? g_XBCv : g_XBCh;
    const float*  conv_w  = dir ? cwv : cwh;
    const float*  conv_b  = dir ? cbv : cbh;
    const float*  dt_bias = dir ? dtbv : dtbh;
    const float*  A_log   = dir ? Alv : Alh;
    const float*  Dv      = dir ? Dv_ : Dh_;
    const float*  norm_w  = dir ? nwv : nwh;
    const int ycol = dir ? 0 : 512;

    int base, stride;
    if (dir) { int b = s >> 6, w = s & 63; base = b * 4096 + w; stride = 64; }
    else     { base = s * 64; stride = 1; }

    __half* XdT = (__half*)(sm + XDT_OFF);
    __half* Bm  = (__half*)(sm + BM_OFF);
    __half* Cm  = (__half*)(sm + CM_OFF);
    float*  G   = (float*)(sm + G_OFF);
    float*  Lc  = (float*)(sm + L_OFF);
    float*  dts = (float*)(sm + DTS_OFF);
    float*  Ddt = (float*)(sm + DDT_OFF);
    float*  nws = (float*)(sm + NW_OFF);
    __half* gsm = (__half*)(sm + GSM_OFF);

    nws[tid] = norm_w[tid];
    ((uint32_t*)sm)[tid] = 0;
    if (tid < 460) ((uint32_t*)sm)[tid + 512] = 0;

#pragma unroll
    for (int j = 0; j < 10; j++) {
        int idx = tid + j * 512;
        int row = idx / 80, c16 = idx % 80;
        uint32_t dst = smb + (uint32_t)(row + 3) * RAW_PITCH + c16 * 16;
        const __half* src = XBC + (size_t)(base + row * stride) * 640 + c16 * 8;
        CP16(dst, src);
    }
    CP_COMMIT();

    // dt / cumsum: warp h handles head h
    if (wid < 8) {
        const int h = wid;
        const float Aneg = -__expf(A_log[h]);
        const float dtb = dt_bias[h];
        const float Dh = Dv[h];
        float v0, v1;
        {
            int t = lane;
            float draw = DT[(size_t)(base + t * stride) * 8 + h] + dtb;
            float dt = (draw > 20.f) ? draw : log1pf(__expf(draw));
            dts[h * 64 + t] = dt; Ddt[h * 64 + t] = Dh / dt;
            v0 = dt * Aneg;
        }
        {
            int t = lane + 32;
            float draw = DT[(size_t)(base + t * stride) * 8 + h] + dtb;
            float dt = (draw > 20.f) ? draw : log1pf(__expf(draw));
            dts[h * 64 + t] = dt; Ddt[h * 64 + t] = Dh / dt;
            v1 = dt * Aneg;
        }
        float a = v0;
#pragma unroll
        for (int o = 1; o < 32; o <<= 1) {
            float u = __shfl_up_sync(0xffffffffu, a, o);
            if (lane >= o) a += u;
        }
        float tot = __shfl_sync(0xffffffffu, a, 31);
        float b = v1;
#pragma unroll
        for (int o = 1; o < 32; o <<= 1) {
            float u = __shfl_up_sync(0xffffffffu, b, o);
            if (lane >= o) b += u;
        }
        b += tot;
        Lc[h * 64 + lane] = a;
        Lc[h * 64 + 32 + lane] = b;
    }
    CP_WAIT(0);
    __syncthreads();

    // conv + SiLU
    {
        const int c = tid, hd = c >> 6;
        const float w0 = conv_w[c * 4], w1 = conv_w[c * 4 + 1];
        const float w2 = conv_w[c * 4 + 2], w3 = conv_w[c * 4 + 3];
        const float cb = conv_b[c];
        const bool isbc = (tid < 128);
        const int c2 = 512 + tid;
        float u0 = 0, u1 = 0, u2 = 0, u3 = 0, ub = 0;
        __half* dstBC = (tid < 64) ? (Bm + tid) : (Cm + (tid - 64));
        if (isbc) {
            u0 = conv_w[c2 * 4]; u1 = conv_w[c2 * 4 + 1];
            u2 = conv_w[c2 * 4 + 2]; u3 = conv_w[c2 * 4 + 3];
            ub = conv_b[c2];
        }
        float r0 = 0, r1 = 0, r2 = 0, q0 = 0, q1 = 0, q2 = 0;
        for (int t = 0; t < SEQ; t++) {
            float cur = __half2float(*(__half*)(sm + (t + 3) * RAW_PITCH + c * 2));
            float v = fmaf(cur, w3, fmaf(r2, w2, fmaf(r1, w1, fmaf(r0, w0, cb))));
            r0 = r1; r1 = r2; r2 = cur;
            v = v / (1.f + __expf(-v));
            XdT[c * 72 + t] = __float2half(v * dts[hd * 64 + t]);
            if (isbc) {
                float cq = __half2float(*(__half*)(sm + (t + 3) * RAW_PITCH + c2 * 2));
                float vq = fmaf(cq, u3, fmaf(q2, u2, fmaf(q1, u1, fmaf(q0, u0, ub))));
                q0 = q1; q1 = q2; q2 = cq;
                vq = vq / (1.f + __expf(-vq));
                dstBC[t * 72] = __float2half(vq);
            }
        }
    }
    __syncthreads();

    // G = C @ B^T (64x64x64); RAW dead now, G lives in the union region
    const int mi = wid & 3, nj = wid >> 2;
    {
        float acc[2][4];
#pragma unroll
        for (int i = 0; i < 2; i++)
#pragma unroll
            for (int j = 0; j < 4; j++) acc[i][j] = 0.f;
#pragma unroll
        for (int ks = 0; ks < 4; ks++) {
            uint32_t a[4], bq[4];
            ldm4(a,  smb + CM_OFF + (mi * 16 + (lane & 15)) * XDT_PITCH + (lane >> 4) * 16 + ks * 32);
            ldm4(bq, smb + BM_OFF + (nj * 16 + (lane & 15)) * XDT_PITCH + (lane >> 4) * 16 + ks * 32);
            mma16816(acc[0], a, bq[0], bq[2]);
            mma16816(acc[1], a, bq[1], bq[3]);
        }
        const int r = lane >> 2, cc = (lane & 3) * 2;
#pragma unroll
        for (int nt = 0; nt < 2; nt++) {
            int sc = nj * 16 + nt * 8 + cc;
            *(float2*)&G[(mi * 16 + r) * G_PITCH + sc]     = make_float2(acc[nt][0], acc[nt][1]);
            *(float2*)&G[(mi * 16 + r + 8) * G_PITCH + sc] = make_float2(acc[nt][2], acc[nt][3]);
        }
    }

    // prefetch Z for head 0
    auto prefetch_z = [&](int h, int buf) {
        int t = tid >> 3, c16 = tid & 7;
        uint32_t dst = smb + ZBUF_OFF + buf * 8192 + t * 128 + c16 * 16;
        const __half* src = Z16 + (size_t)(base + t * stride) * 512 + h * 64 + c16 * 8;
        CP16(dst, src);
        CP_COMMIT();
    };
    prefetch_z(0, 0);
    __syncthreads();

    // per-head masked GEMMs
    for (int h = 0; h < 8; h++) {
        if (h < 7) { prefetch_z(h + 1, (h + 1) & 1); CP_WAIT(1); }
        else       { CP_WAIT(0); }

        const float* Lh = Lc + h * 64;
        __half* Gmh = (__half*)(sm + GMH_OFF);
        __half* Gml = (__half*)(sm + GML_OFF);
#pragma unroll
        for (int k = 0; k < 8; k++) {
            int idx = tid + k * 512;
            int t = idx >> 6, sc = idx & 63;
            float w = 0.f;
            if (sc <= t) w = __expf(Lh[t] - Lh[sc]);
            float gm = G[t * G_PITCH + sc] * w;
            if (sc == t) gm += Ddt[h * 64 + t];
            __half hi = __float2half(gm);
            Gmh[t * 72 + sc] = hi;
            Gml[t * 72 + sc] = __float2half(gm - __half2float(hi));
        }
        __syncthreads();

        float acc[2][4];
#pragma unroll
        for (int i = 0; i < 2; i++)
#pragma unroll
            for (int j = 0; j < 4; j++) acc[i][j] = 0.f;
#pragma unroll
        for (int ks = 0; ks < 4; ks++) {
            uint32_t ah[4], al[4], bq[4];
            uint32_t ro = (mi * 16 + (lane & 15)) * XDT_PITCH + (lane >> 4) * 16 + ks * 32;
            ldm4(ah, smb + GMH_OFF + ro);
            ldm4(al, smb + GML_OFF + ro);
            ldm4(bq, smb + XDT_OFF + (uint32_t)(h * 64 + nj * 16 + (lane & 15)) * XDT_PITCH
                        + (lane >> 4) * 16 + ks * 32);
            mma16816(acc[0], ah, bq[0], bq[2]);
            mma16816(acc[1], ah, bq[1], bq[3]);
            mma16816(acc[0], al, bq[0], bq[2]);
            mma16816(acc[1], al, bq[1], bq[3]);
        }
        const int r = lane >> 2, cc = (lane & 3) * 2;
        const char* zbase = sm + ZBUF_OFF + (h & 1) * 8192;
#pragma unroll
        for (int nt = 0; nt < 2; nt++)
#pragma unroll
            for (int rr = 0; rr < 2; rr++) {
                int t = mi * 16 + r + rr * 8;
                int p = nj * 16 + nt * 8 + cc;
                float y0 = acc[nt][rr * 2 + 0], y1 = acc[nt][rr * 2 + 1];
                __half2 zv = *(__half2*)(zbase + t * 128 + p * 2);
                float z0 = __half2float(zv.x), z1 = __half2float(zv.y);
                float g0 = y0 * z0 / (1.f + __expf(-z0));
                float g1 = y1 * z1 / (1.f + __expf(-z1));
                *(__half2*)&gsm[t * GSM_PITCH + h * 64 + p] = __floats2half2_rn(g0, g1);
            }
        __syncthreads();
    }

    // RMS norm + output
#pragma unroll
    for (int k = 0; k < 4; k++) {
        int t = wid + k * 16;
        float ss = 0.f;
        float2 gv[8];
#pragma unroll
        for (int j = 0; j < 8; j++) {
            __half2 hv = *(__half2*)&gsm[t * GSM_PITCH + j * 64 + lane * 2];
            float a = __half2float(hv.x), b = __half2float(hv.y);
            gv[j] = make_float2(a, b);
            ss = fmaf(a, a, ss); ss = fmaf(b, b, ss);
        }
#pragma unroll
        for (int o = 16; o; o >>= 1) ss += __shfl_xor_sync(0xffffffffu, ss, o);
        float sinv = rsqrtf(ss * (1.0f / 512.0f) + 1e-5f);
        size_t orow = (size_t)(base + t * stride) * KFIN + ycol;
#pragma unroll
        for (int j = 0; j < 8; j++) {
            int c = j * 64 + lane * 2;
            float a = gv[j].x * sinv * nws[c];
            float b = gv[j].y * sinv * nws[c + 1];
            *(__half2*)&g_Y[orow + c] = __floats2half2_rn(a, b);
        }
    }
}

// ---------------- fold fc_w into out_w -----------------------------------------
__global__ void __launch_bounds__(256) wcomb_kernel(
    const float* __restrict__ mh_out_w, const float* __restrict__ mv_out_w,
    const float* __restrict__ fc_w)
{
    const int d  = blockIdx.x;
    const int k0 = blockIdx.y * 64;
    const int nb = blockIdx.z * 32;
    const float* ow = d ? mh_out_w : mv_out_w;
    const int fo = d ? 512 : 0;
    __shared__ float ows[64][65];
    __shared__ float fs[32][65];
    const int kk = threadIdx.x & 63;
    const int ng = threadIdx.x >> 6;
    float acc[8];
#pragma unroll
    for (int i = 0; i < 8; i++) acc[i] = 0.f;

    for (int jo = 0; jo < 256; jo += 64) {
        for (int idx = threadIdx.x; idx < 64 * 64; idx += 256) {
            int j = idx >> 6, c = idx & 63;
            ows[j][c] = ow[(size_t)(jo + j) * 512 + k0 + c];
        }
        for (int idx = threadIdx.x; idx < 32 * 64; idx += 256) {
            int n = idx >> 6, jj = idx & 63;
            fs[n][jj] = fc_w[(size_t)(nb + n) * 1024 + fo + jo + jj] +
                        fc_w[(size_t)(nb + n) * 1024 + fo + 256 + jo + jj];
        }
        __syncthreads();
#pragma unroll 4
        for (int j = 0; j < 64; j++) {
            float o = ows[j][kk];
#pragma unroll
            for (int i = 0; i < 8; i++)
                acc[i] = fmaf(o, fs[ng * 8 + i][j], acc[i]);
        }
        __syncthreads();
    }
#pragma unroll
    for (int i = 0; i < 8; i++) {
        float val = acc[i];
        __half hh = __float2half(val);
        size_t idx = (size_t)(nb + ng * 8 + i) * KFIN + d * 512 + (k0 + kk);
        g_WcBhi[idx] = hh;
        g_WcBlo[idx] = __float2half(val - __half2float(hh));
    }
}

// ---------------- launch ----------------
extern "C" void kernel_launch(void* const* d_in, const int* in_sizes, int n_in,
                              void* d_out, int out_size)
{
    (void)in_sizes; (void)n_in; (void)out_size;
    const float* x          = (const float*)d_in[0];
    const float* mh_in_w    = (const float*)d_in[1];
    const float* mh_conv_w  = (const float*)d_in[2];
    const float* mh_conv_b  = (const float*)d_in[3];
    const float* mh_dt_bias = (const float*)d_in[4];
    const float* mh_A_log   = (const float*)d_in[5];
    const float* mh_D       = (const float*)d_in[6];
    const float* mh_norm_w  = (const float*)d_in[7];
    const float* mh_out_w   = (const float*)d_in[8];
    const float* mv_in_w    = (const float*)d_in[9];
    const float* mv_conv_w  = (const float*)d_in[10];
    const float* mv_conv_b  = (const float*)d_in[11];
    const float* mv_dt_bias = (const float*)d_in[12];
    const float* mv_A_log   = (const float*)d_in[13];
    const float* mv_D       = (const float*)d_in[14];
    const float* mv_norm_w  = (const float*)d_in[15];
    const float* mv_out_w   = (const float*)d_in[16];
    const float* fc_w       = (const float*)d_in[17];
    const float* fc_b       = (const float*)d_in[18];
    float* out = (float*)d_out;

    __half *Z16h, *Z16v, *XBCh, *XBCv, *Xhi, *Whhi, *Wvhi, *Y, *WcBhi, *WcBlo;
    cudaGetSymbolAddress((void**)&Z16h, g_Z16h);
    cudaGetSymbolAddress((void**)&Z16v, g_Z16v);
    cudaGetSymbolAddress((void**)&XBCh, g_XBCh);
    cudaGetSymbolAddress((void**)&XBCv, g_XBCv);
    cudaGetSymbolAddress((void**)&Xhi,  g_Xhi);
    cudaGetSymbolAddress((void**)&Whhi, g_Whhi);
    cudaGetSymbolAddress((void**)&Wvhi, g_Wvhi);
    cudaGetSymbolAddress((void**)&Y,    g_Y);
    cudaGetSymbolAddress((void**)&WcBhi, g_WcBhi);
    cudaGetSymbolAddress((void**)&WcBlo, g_WcBlo);

    cudaFuncSetAttribute(gemm_mma, cudaFuncAttributeMaxDynamicSharedMemorySize, GSMEM);
    cudaFuncSetAttribute(ssd_kernel, cudaFuncAttributeMaxDynamicSharedMemorySize, SSD_SMEM);

    cvt_x_kernel<<<NTOK * D_MODEL / 4 / 256, 256>>>(x);
    prep_w_kernel<<<(NIN * D_MODEL + 255) / 256, 256>>>(mh_in_w, mv_in_w);
    wcomb_kernel<<<dim3(2, 8, 8), 256>>>(mh_out_w, mv_out_w, fc_w);
    dt_kernel<<<NTOK / 32, 256>>>(x, mh_in_w + 1152 * 256, mv_in_w + 1152 * 256);

    gemm_mma<<<dim3(NTOK / BMg, NIN / BNg, 2), 256, GSMEM>>>(
        Xhi, Whhi, Whhi, Wvhi, Wvhi, nullptr,
        Z16h, XBCh, Z16v, XBCv, D_MODEL, 0, nullptr, 1);

    ssd_kernel<<<2 * NSEQ, 512, SSD_SMEM>>>(
        mh_conv_w, mh_conv_b, mh_dt_bias, mh_A_log, mh_D, mh_norm_w,
        mv_conv_w, mv_conv_b, mv_dt_bias, mv_A_log, mv_D, mv_norm_w);

    gemm_mma<<<dim3(NTOK / BMg, D_MODEL / BNg, 1), 256, GSMEM>>>(
        Y, WcBhi, WcBlo, WcBhi, WcBlo, out,
        nullptr, nullptr, nullptr, nullptr, KFIN, D_MODEL, fc_b, 0);
}

// round 15
// speedup vs baseline: 2.7052x; 1.0973x over previous
#include <cuda_runtime.h>
#include <cuda_bf16.h>
#include <cuda_fp16.h>
#include <math.h>
#include <stdint.h>

#define D_MODEL   256
#define D_INNER   512
#define CONV_CH   640
#define SEQ       64
#define NSEQ      512
#define NTOK      32768
#define KFIN      1024
#define NIN       1152

// ---------------- scratch ------------------------------------------------------
__device__ __half g_Z16h[(size_t)NTOK * D_INNER];
__device__ __half g_Z16v[(size_t)NTOK * D_INNER];
__device__ float  g_dth [(size_t)NTOK * 8];
__device__ float  g_dtv [(size_t)NTOK * 8];
__device__ __half g_XBCh[(size_t)NTOK * CONV_CH];
__device__ __half g_XBCv[(size_t)NTOK * CONV_CH];
__device__ __half g_Xhi [(size_t)NTOK * D_MODEL];
__device__ __half g_Whhi[(size_t)NIN * D_MODEL];
__device__ __half g_Wvhi[(size_t)NIN * D_MODEL];
__device__ __half g_Y   [(size_t)NTOK * KFIN];
__device__ __half g_WcBhi[(size_t)D_MODEL * KFIN];

extern __shared__ char dynsm[];

// ---------------- helpers ------------------------------------------------------
__device__ __forceinline__ uint32_t smem_u32(const void* p) {
    uint32_t a;
    asm("{ .reg .u64 t; cvta.to.shared.u64 t, %1; cvt.u32.u64 %0, t; }" : "=r"(a) : "l"(p));
    return a;
}
__device__ __forceinline__ uint32_t swz128(uint32_t off) {
    return off ^ ((off >> 3) & 0x70);
}
#define CP16(dst, src) \
    asm volatile("cp.async.cg.shared.global [%0], [%1], 16;" :: "r"(dst), "l"(src))
#define CP_COMMIT() asm volatile("cp.async.commit_group;" ::: "memory")
#define CP_WAIT(n)  asm volatile("cp.async.wait_group %0;" :: "n"(n) : "memory")

__device__ __forceinline__ void ldm4(uint32_t* r, uint32_t addr) {
    asm volatile("ldmatrix.sync.aligned.m8n8.x4.shared.b16 {%0,%1,%2,%3}, [%4];"
        : "=r"(r[0]), "=r"(r[1]), "=r"(r[2]), "=r"(r[3]) : "r"(addr));
}
__device__ __forceinline__ void mma16816(float* d, const uint32_t* a, uint32_t b0, uint32_t b1) {
    asm volatile("mma.sync.aligned.m16n8k16.row.col.f32.f16.f16.f32 "
        "{%0,%1,%2,%3}, {%4,%5,%6,%7}, {%8,%9}, {%0,%1,%2,%3};"
        : "+f"(d[0]), "+f"(d[1]), "+f"(d[2]), "+f"(d[3])
        : "r"(a[0]), "r"(a[1]), "r"(a[2]), "r"(a[3]), "r"(b0), "r"(b1));
}

// ---------------- prep kernels --------------------------------------------------
__global__ void prep_w_kernel(const float* __restrict__ wh, const float* __restrict__ wv) {
    int i = blockIdx.x * 256 + threadIdx.x;
    if (i < NIN * D_MODEL) {
        g_Whhi[i] = __float2half(wh[i]);
        g_Wvhi[i] = __float2half(wv[i]);
    }
}

// fused: x -> fp16 Xhi  +  exact fp32 dt (both dirs)
__global__ void __launch_bounds__(256) cvtdt_kernel(
    const float* __restrict__ x,
    const float* __restrict__ whd, const float* __restrict__ wvd)
{
    __shared__ float xs[32][260];
    __shared__ float wh[8][260];
    __shared__ float wv[8][260];
    const int tid = threadIdx.x;
    const int row0 = blockIdx.x * 32;
    for (int i = tid; i < 8 * 64; i += 256) {
        int h = i >> 6, c4 = (i & 63) * 4;
        *(float4*)&wh[h][c4] = *(const float4*)&whd[h * 256 + c4];
        *(float4*)&wv[h][c4] = *(const float4*)&wvd[h * 256 + c4];
    }
    for (int i = tid; i < 32 * 64; i += 256) {
        int r = i >> 6, c4 = (i & 63) * 4;
        *(float4*)&xs[r][c4] = *(const float4*)&x[(size_t)(row0 + r) * 256 + c4];
    }
    __syncthreads();
    // fp16 conversion out of smem
    for (int i = tid; i < 32 * 64; i += 256) {
        int r = i >> 6, c4 = (i & 63) * 4;
        float4 v = *(float4*)&xs[r][c4];
        size_t o = ((size_t)(row0 + r) * 256 + c4) >> 1;
        ((__half2*)g_Xhi)[o]     = __floats2half2_rn(v.x, v.y);
        ((__half2*)g_Xhi)[o + 1] = __floats2half2_rn(v.z, v.w);
    }
    const int r = tid >> 3, h = tid & 7;
    float ah = 0.f, av = 0.f;
#pragma unroll 8
    for (int k = 0; k < 256; k += 4) {
        float4 xv = *(float4*)&xs[r][k];
        float4 wa = *(float4*)&wh[h][k];
        float4 wb = *(float4*)&wv[h][k];
        ah = fmaf(xv.x, wa.x, ah); ah = fmaf(xv.y, wa.y, ah);
        ah = fmaf(xv.z, wa.z, ah); ah = fmaf(xv.w, wa.w, ah);
        av = fmaf(xv.x, wb.x, av); av = fmaf(xv.y, wb.y, av);
        av = fmaf(xv.z, wb.z, av); av = fmaf(xv.w, wb.w, av);
    }
    g_dth[(size_t)(row0 + r) * 8 + h] = ah;
    g_dtv[(size_t)(row0 + r) * 8 + h] = av;
}

// ---------------- mma.sync fp16 GEMM, 1-term, BK=64, 3-stage --------------------
// mode==1 (in-proj): fp16 out (Z16 / XBC split)
// mode==0 (final)  : fp32 out + bias
#define BMg 128
#define BNg 128
#define TILE64_B 16384
#define STAGE_B  32768
#define GSMEM    98304

__global__ void __launch_bounds__(256, 2) gemm_mma(
    const __half* __restrict__ A,
    const __half* __restrict__ B0, const __half* __restrict__ B1,
    float* __restrict__ C,
    __half* __restrict__ Z0, __half* __restrict__ X0,
    __half* __restrict__ Z1, __half* __restrict__ X1,
    int K, int ldc, const float* __restrict__ bias, int mode)
{
    const uint32_t smb = smem_u32(dynsm);
    const int tid = threadIdx.x, lane = tid & 31, wid = tid >> 5;
    const int m0 = blockIdx.x * BMg, n0 = blockIdx.y * BNg;
    const int wm = (wid & 1) * 64, wn = 32 * (wid >> 1);
    const int nk = K >> 6;

    const __half* B = blockIdx.z ? B1 : B0;
    __half* Z16 = blockIdx.z ? Z1 : Z0;
    __half* XB  = blockIdx.z ? X1 : X0;

    uint32_t arow[4], brow[2];
#pragma unroll
    for (int mt = 0; mt < 4; mt++)
        arow[mt] = (uint32_t)(wm + mt * 16 + (lane & 15)) * 128 + (lane >> 4) * 16;
#pragma unroll
    for (int nb = 0; nb < 2; nb++)
        brow[nb] = (uint32_t)(wn + nb * 16 + (lane & 15)) * 128 + (lane >> 4) * 16;

    float acc[4][4][4];
#pragma unroll
    for (int a = 0; a < 4; a++)
#pragma unroll
        for (int b = 0; b < 4; b++)
#pragma unroll
            for (int c = 0; c < 4; c++) acc[a][b][c] = 0.f;

    const int lrow = tid >> 1, cq = (tid & 1) * 4;

    auto load_stage = [&](int s, int c) {
        const int koff = c * 64;
        const uint32_t base = smb + s * STAGE_B;
        const __half* pA = A + (size_t)(m0 + lrow) * K + koff;
        const __half* pB = B + (size_t)(n0 + lrow) * K + koff;
        const uint32_t rb = (uint32_t)lrow * 128;
#pragma unroll
        for (int ch = 0; ch < 4; ch++) {
            uint32_t d = swz128(rb + (cq + ch) * 16);
            CP16(base + d, pA + (cq + ch) * 8);
            CP16(base + TILE64_B + d, pB + (cq + ch) * 8);
        }
        CP_COMMIT();
    };

    load_stage(0, 0);
    load_stage(1, 1);

    for (int c = 0; c < nk; c++) {
        if (c + 1 < nk) CP_WAIT(1); else CP_WAIT(0);
        __syncthreads();
        if (c + 2 < nk) load_stage((c + 2) % 3, c + 2);

        const uint32_t base = smb + (c % 3) * STAGE_B;
        const uint32_t aB = base, bB = base + TILE64_B;
#pragma unroll
        for (int ks = 0; ks < 4; ks++) {
            uint32_t af[4][4], bf[2][4];
#pragma unroll
            for (int mt = 0; mt < 4; mt++)
                ldm4(af[mt], aB + swz128(arow[mt] + ks * 32));
#pragma unroll
            for (int nb = 0; nb < 2; nb++)
                ldm4(bf[nb], bB + swz128(brow[nb] + ks * 32));
#pragma unroll
            for (int mt = 0; mt < 4; mt++)
#pragma unroll
                for (int nb = 0; nb < 2; nb++) {
                    mma16816(acc[mt][nb * 2],     af[mt], bf[nb][0], bf[nb][2]);
                    mma16816(acc[mt][nb * 2 + 1], af[mt], bf[nb][1], bf[nb][3]);
                }
        }
    }

#pragma unroll
    for (int mt = 0; mt < 4; mt++) {
        int row = m0 + wm + mt * 16 + (lane >> 2);
#pragma unroll
        for (int nt = 0; nt < 4; nt++) {
            int col = n0 + wn + nt * 8 + (lane & 3) * 2;
            float2 v0 = make_float2(acc[mt][nt][0], acc[mt][nt][1]);
            float2 v1 = make_float2(acc[mt][nt][2], acc[mt][nt][3]);
            if (mode == 1) {
                if (col < 512) {
                    *(__half2*)&Z16[(size_t)row * 512 + col]       = __floats2half2_rn(v0.x, v0.y);
                    *(__half2*)&Z16[(size_t)(row + 8) * 512 + col] = __floats2half2_rn(v1.x, v1.y);
                } else {
                    int xc = col - 512;
                    *(__half2*)&XB[(size_t)row * 640 + xc]       = __floats2half2_rn(v0.x, v0.y);
                    *(__half2*)&XB[(size_t)(row + 8) * 640 + xc] = __floats2half2_rn(v1.x, v1.y);
                }
            } else {
                float b0 = bias[col], b1 = bias[col + 1];
                v0.x += b0; v0.y += b1; v1.x += b0; v1.y += b1;
                *(float2*)&C[(size_t)row * ldc + col] = v0;
                *(float2*)&C[(size_t)(row + 8) * ldc + col] = v1;
            }
        }
    }
}

// ---------------- SSD kernel ----------------------------------------------------
#define RAW_PITCH 1296
#define XDT_PITCH 144
#define G_PITCH   68
#define GSM_PITCH 520

#define GSM_OFF   0
#define G_OFF     66560
#define XDT_OFF   86832
#define BM_OFF    160560
#define CM_OFF    169776
#define GMH_OFF   178992
#define GML_OFF   188208
#define ZBUF_OFF  197424
#define L_OFF     213808
#define DTS_OFF   215856
#define DDT_OFF   217904
#define NW_OFF    219952
#define SSD_SMEM  222000

__global__ void __launch_bounds__(512, 1) ssd_kernel(
    const float* __restrict__ cwh, const float* __restrict__ cbh,
    const float* __restrict__ dtbh, const float* __restrict__ Alh,
    const float* __restrict__ Dh_, const float* __restrict__ nwh,
    const float* __restrict__ cwv, const float* __restrict__ cbv,
    const float* __restrict__ dtbv, const float* __restrict__ Alv,
    const float* __restrict__ Dv_, const float* __restrict__ nwv)
{
    char* sm = dynsm;
    const uint32_t smb = smem_u32(sm);
    const int tid = threadIdx.x, lane = tid & 31, wid = tid >> 5;
    const int dir = blockIdx.x >> 9;
    const int s   = blockIdx.x & 511;

    const __half* Z16     = dir ? g_Z16v : g_Z16h;
    const float*  DT      = dir ? g_dtv : g_dth;
    const __half* XBC     = dir ? g_XBCv : g_XBCh;
    const float*  conv_w  = dir ? cwv : cwh;
    const float*  conv_b  = dir ? cbv : cbh;
    const float*  dt_bias = dir ? dtbv : dtbh;
    const float*  A_log   = dir ? Alv : Alh;
    const float*  Dv      = dir ? Dv_ : Dh_;
    const float*  norm_w  = dir ? nwv : nwh;
    const int ycol = dir ? 0 : 512;

    int base, stride;
    if (dir) { int b = s >> 6, w = s & 63; base = b * 4096 + w; stride = 64; }
    else     { base = s * 64; stride = 1; }

    __half* XdT = (__half*)(sm + XDT_OFF);
    __half* Bm  = (__half*)(sm + BM_OFF);
    __half* Cm  = (__half*)(sm + CM_OFF);
    float*  G   = (float*)(sm + G_OFF);
    float*  Lc  = (float*)(sm + L_OFF);
    float*  dts = (float*)(sm + DTS_OFF);
    float*  Ddt = (float*)(sm + DDT_OFF);
    float*  nws = (float*)(sm + NW_OFF);
    __half* gsm = (__half*)(sm + GSM_OFF);

    nws[tid] = norm_w[tid];
    ((uint32_t*)sm)[tid] = 0;
    if (tid < 460) ((uint32_t*)sm)[tid + 512] = 0;

#pragma unroll
    for (int j = 0; j < 10; j++) {
        int idx = tid + j * 512;
        int row = idx / 80, c16 = idx % 80;
        uint32_t dst = smb + (uint32_t)(row + 3) * RAW_PITCH + c16 * 16;
        const __half* src = XBC + (size_t)(base + row * stride) * 640 + c16 * 8;
        CP16(dst, src);
    }
    CP_COMMIT();

    if (wid < 8) {
        const int h = wid;
        const float Aneg = -__expf(A_log[h]);
        const float dtb = dt_bias[h];
        const float Dh = Dv[h];
        float v0, v1;
        {
            int t = lane;
            float draw = DT[(size_t)(base + t * stride) * 8 + h] + dtb;
            float dt = (draw > 20.f) ? draw : log1pf(__expf(draw));
            dts[h * 64 + t] = dt; Ddt[h * 64 + t] = Dh / dt;
            v0 = dt * Aneg;
        }
        {
            int t = lane + 32;
            float draw = DT[(size_t)(base + t * stride) * 8 + h] + dtb;
            float dt = (draw > 20.f) ? draw : log1pf(__expf(draw));
            dts[h * 64 + t] = dt; Ddt[h * 64 + t] = Dh / dt;
            v1 = dt * Aneg;
        }
        float a = v0;
#pragma unroll
        for (int o = 1; o < 32; o <<= 1) {
            float u = __shfl_up_sync(0xffffffffu, a, o);
            if (lane >= o) a += u;
        }
        float tot = __shfl_sync(0xffffffffu, a, 31);
        float b = v1;
#pragma unroll
        for (int o = 1; o < 32; o <<= 1) {
            float u = __shfl_up_sync(0xffffffffu, b, o);
            if (lane >= o) b += u;
        }
        b += tot;
        Lc[h * 64 + lane] = a;
        Lc[h * 64 + 32 + lane] = b;
    }
    CP_WAIT(0);
    __syncthreads();

    {
        const int c = tid, hd = c >> 6;
        const float w0 = conv_w[c * 4], w1 = conv_w[c * 4 + 1];
        const float w2 = conv_w[c * 4 + 2], w3 = conv_w[c * 4 + 3];
        const float cb = conv_b[c];
        const bool isbc = (tid < 128);
        const int c2 = 512 + tid;
        float u0 = 0, u1 = 0, u2 = 0, u3 = 0, ub = 0;
        __half* dstBC = (tid < 64) ? (Bm + tid) : (Cm + (tid - 64));
        if (isbc) {
            u0 = conv_w[c2 * 4]; u1 = conv_w[c2 * 4 + 1];
            u2 = conv_w[c2 * 4 + 2]; u3 = conv_w[c2 * 4 + 3];
            ub = conv_b[c2];
        }
        float r0 = 0, r1 = 0, r2 = 0, q0 = 0, q1 = 0, q2 = 0;
        for (int t = 0; t < SEQ; t++) {
            float cur = __half2float(*(__half*)(sm + (t + 3) * RAW_PITCH + c * 2));
            float v = fmaf(cur, w3, fmaf(r2, w2, fmaf(r1, w1, fmaf(r0, w0, cb))));
            r0 = r1; r1 = r2; r2 = cur;
            v = v / (1.f + __expf(-v));
            XdT[c * 72 + t] = __float2half(v * dts[hd * 64 + t]);
            if (isbc) {
                float cq = __half2float(*(__half*)(sm + (t + 3) * RAW_PITCH + c2 * 2));
                float vq = fmaf(cq, u3, fmaf(q2, u2, fmaf(q1, u1, fmaf(q0, u0, ub))));
                q0 = q1; q1 = q2; q2 = cq;
                vq = vq / (1.f + __expf(-vq));
                dstBC[t * 72] = __float2half(vq);
            }
        }
    }
    __syncthreads();

    const int mi = wid & 3, nj = wid >> 2;
    {
        float acc[2][4];
#pragma unroll
        for (int i = 0; i < 2; i++)
#pragma unroll
            for (int j = 0; j < 4; j++) acc[i][j] = 0.f;
#pragma unroll
        for (int ks = 0; ks < 4; ks++) {
            uint32_t a[4], bq[4];
            ldm4(a,  smb + CM_OFF + (mi * 16 + (lane & 15)) * XDT_PITCH + (lane >> 4) * 16 + ks * 32);
            ldm4(bq, smb + BM_OFF + (nj * 16 + (lane & 15)) * XDT_PITCH + (lane >> 4) * 16 + ks * 32);
            mma16816(acc[0], a, bq[0], bq[2]);
            mma16816(acc[1], a, bq[1], bq[3]);
        }
        const int r = lane >> 2, cc = (lane & 3) * 2;
#pragma unroll
        for (int nt = 0; nt < 2; nt++) {
            int sc = nj * 16 + nt * 8 + cc;
            *(float2*)&G[(mi * 16 + r) * G_PITCH + sc]     = make_float2(acc[nt][0], acc[nt][1]);
            *(float2*)&G[(mi * 16 + r + 8) * G_PITCH + sc] = make_float2(acc[nt][2], acc[nt][3]);
        }
    }

    auto prefetch_z = [&](int h, int buf) {
        int t = tid >> 3, c16 = tid & 7;
        uint32_t dst = smb + ZBUF_OFF + buf * 8192 + t * 128 + c16 * 16;
        const __half* src = Z16 + (size_t)(base + t * stride) * 512 + h * 64 + c16 * 8;
        CP16(dst, src);
        CP_COMMIT();
    };
    prefetch_z(0, 0);
    __syncthreads();

    for (int h = 0; h < 8; h++) {
        if (h < 7) { prefetch_z(h + 1, (h + 1) & 1); CP_WAIT(1); }
        else       { CP_WAIT(0); }

        const float* Lh = Lc + h * 64;
        __half* Gmh = (__half*)(sm + GMH_OFF);
        __half* Gml = (__half*)(sm + GML_OFF);
#pragma unroll
        for (int k = 0; k < 8; k++) {
            int idx = tid + k * 512;
            int t = idx >> 6, sc = idx & 63;
            float w = 0.f;
            if (sc <= t) w = __expf(Lh[t] - Lh[sc]);
            float gm = G[t * G_PITCH + sc] * w;
            if (sc == t) gm += Ddt[h * 64 + t];
            __half hi = __float2half(gm);
            Gmh[t * 72 + sc] = hi;
            Gml[t * 72 + sc] = __float2half(gm - __half2float(hi));
        }
        __syncthreads();

        float acc[2][4];
#pragma unroll
        for (int i = 0; i < 2; i++)
#pragma unroll
            for (int j = 0; j < 4; j++) acc[i][j] = 0.f;
#pragma unroll
        for (int ks = 0; ks < 4; ks++) {
            uint32_t ah[4], al[4], bq[4];
            uint32_t ro = (mi * 16 + (lane & 15)) * XDT_PITCH + (lane >> 4) * 16 + ks * 32;
            ldm4(ah, smb + GMH_OFF + ro);
            ldm4(al, smb + GML_OFF + ro);
            ldm4(bq, smb + XDT_OFF + (uint32_t)(h * 64 + nj * 16 + (lane & 15)) * XDT_PITCH
                        + (lane >> 4) * 16 + ks * 32);
            mma16816(acc[0], ah, bq[0], bq[2]);
            mma16816(acc[1], ah, bq[1], bq[3]);
            mma16816(acc[0], al, bq[0], bq[2]);
            mma16816(acc[1], al, bq[1], bq[3]);
        }
        const int r = lane >> 2, cc = (lane & 3) * 2;
        const char* zbase = sm + ZBUF_OFF + (h & 1) * 8192;
#pragma unroll
        for (int nt = 0; nt < 2; nt++)
#pragma unroll
            for (int rr = 0; rr < 2; rr++) {
                int t = mi * 16 + r + rr * 8;
                int p = nj * 16 + nt * 8 + cc;
                float y0 = acc[nt][rr * 2 + 0], y1 = acc[nt][rr * 2 + 1];
                __half2 zv = *(__half2*)(zbase + t * 128 + p * 2);
                float z0 = __half2float(zv.x), z1 = __half2float(zv.y);
                float g0 = y0 * z0 / (1.f + __expf(-z0));
                float g1 = y1 * z1 / (1.f + __expf(-z1));
                *(__half2*)&gsm[t * GSM_PITCH + h * 64 + p] = __floats2half2_rn(g0, g1);
            }
        __syncthreads();
    }

#pragma unroll
    for (int k = 0; k < 4; k++) {
        int t = wid + k * 16;
        float ss = 0.f;
        float2 gv[8];
#pragma unroll
        for (int j = 0; j < 8; j++) {
            __half2 hv = *(__half2*)&gsm[t * GSM_PITCH + j * 64 + lane * 2];
            float a = __half2float(hv.x), b = __half2float(hv.y);
            gv[j] = make_float2(a, b);
            ss = fmaf(a, a, ss); ss = fmaf(b, b, ss);
        }
#pragma unroll
        for (int o = 16; o; o >>= 1) ss += __shfl_xor_sync(0xffffffffu, ss, o);
        float sinv = rsqrtf(ss * (1.0f / 512.0f) + 1e-5f);
        size_t orow = (size_t)(base + t * stride) * KFIN + ycol;
#pragma unroll
        for (int j = 0; j < 8; j++) {
            int c = j * 64 + lane * 2;
            float a = gv[j].x * sinv * nws[c];
            float b = gv[j].y * sinv * nws[c + 1];
            *(__half2*)&g_Y[orow + c] = __floats2half2_rn(a, b);
        }
    }
}

// ---------------- fold fc_w into out_w (fp16 out, 256 blocks) -------------------
__global__ void __launch_bounds__(256) wcomb_kernel(
    const float* __restrict__ mh_out_w, const float* __restrict__ mv_out_w,
    const float* __restrict__ fc_w)
{
    const int d  = blockIdx.x;
    const int k0 = blockIdx.y * 32;
    const int nb = blockIdx.z * 32;
    const float* ow = d ? mh_out_w : mv_out_w;
    const int fo = d ? 512 : 0;
    __shared__ float ows[64][33];
    __shared__ float fs[32][65];
    const int kk = threadIdx.x & 31;
    const int ng = threadIdx.x >> 5;       // 0..7, 4 n each
    float acc[4];
#pragma unroll
    for (int i = 0; i < 4; i++) acc[i] = 0.f;

    for (int jo = 0; jo < 256; jo += 64) {
        for (int idx = threadIdx.x; idx < 64 * 32; idx += 256) {
            int j = idx >> 5, k = idx & 31;
            ows[j][k] = ow[(size_t)(jo + j) * 512 + k0 + k];
        }
        for (int idx = threadIdx.x; idx < 32 * 64; idx += 256) {
            int n = idx >> 6, jj = idx & 63;
            fs[n][jj] = fc_w[(size_t)(nb + n) * 1024 + fo + jo + jj] +
                        fc_w[(size_t)(nb + n) * 1024 + fo + 256 + jo + jj];
        }
        __syncthreads();
#pragma unroll 4
        for (int j = 0; j < 64; j++) {
            float o = ows[j][kk];
#pragma unroll
            for (int i = 0; i < 4; i++)
                acc[i] = fmaf(o, fs[ng * 4 + i][j], acc[i]);
        }
        __syncthreads();
    }
#pragma unroll
    for (int i = 0; i < 4; i++)
        g_WcBhi[(size_t)(nb + ng * 4 + i) * KFIN + d * 512 + (k0 + kk)] = __float2half(acc[i]);
}

// ---------------- launch ----------------
extern "C" void kernel_launch(void* const* d_in, const int* in_sizes, int n_in,
                              void* d_out, int out_size)
{
    (void)in_sizes; (void)n_in; (void)out_size;
    const float* x          = (const float*)d_in[0];
    const float* mh_in_w    = (const float*)d_in[1];
    const float* mh_conv_w  = (const float*)d_in[2];
    const float* mh_conv_b  = (const float*)d_in[3];
    const float* mh_dt_bias = (const float*)d_in[4];
    const float* mh_A_log   = (const float*)d_in[5];
    const float* mh_D       = (const float*)d_in[6];
    const float* mh_norm_w  = (const float*)d_in[7];
    const float* mh_out_w   = (const float*)d_in[8];
    const float* mv_in_w    = (const float*)d_in[9];
    const float* mv_conv_w  = (const float*)d_in[10];
    const float* mv_conv_b  = (const float*)d_in[11];
    const float* mv_dt_bias = (const float*)d_in[12];
    const float* mv_A_log   = (const float*)d_in[13];
    const float* mv_D       = (const float*)d_in[14];
    const float* mv_norm_w  = (const float*)d_in[15];
    const float* mv_out_w   = (const float*)d_in[16];
    const float* fc_w       = (const float*)d_in[17];
    const float* fc_b       = (const float*)d_in[18];
    float* out = (float*)d_out;

    __half *Z16h, *Z16v, *XBCh, *XBCv, *Xhi, *Whhi, *Wvhi, *Y, *WcBhi;
    cudaGetSymbolAddress((void**)&Z16h, g_Z16h);
    cudaGetSymbolAddress((void**)&Z16v, g_Z16v);
    cudaGetSymbolAddress((void**)&XBCh, g_XBCh);
    cudaGetSymbolAddress((void**)&XBCv, g_XBCv);
    cudaGetSymbolAddress((void**)&Xhi,  g_Xhi);
    cudaGetSymbolAddress((void**)&Whhi, g_Whhi);
    cudaGetSymbolAddress((void**)&Wvhi, g_Wvhi);
    cudaGetSymbolAddress((void**)&Y,    g_Y);
    cudaGetSymbolAddress((void**)&WcBhi, g_WcBhi);

    cudaFuncSetAttribute(gemm_mma, cudaFuncAttributeMaxDynamicSharedMemorySize, GSMEM);
    cudaFuncSetAttribute(ssd_kernel, cudaFuncAttributeMaxDynamicSharedMemorySize, SSD_SMEM);

    prep_w_kernel<<<(NIN * D_MODEL + 255) / 256, 256>>>(mh_in_w, mv_in_w);
    wcomb_kernel<<<dim3(2, 16, 8), 256>>>(mh_out_w, mv_out_w, fc_w);
    cvtdt_kernel<<<NTOK / 32, 256>>>(x, mh_in_w + 1152 * 256, mv_in_w + 1152 * 256);

    gemm_mma<<<dim3(NTOK / BMg, NIN / BNg, 2), 256, GSMEM>>>(
        Xhi, Whhi, Wvhi, nullptr,
        Z16h, XBCh, Z16v, XBCv, D_MODEL, 0, nullptr, 1);

    ssd_kernel<<<2 * NSEQ, 512, SSD_SMEM>>>(
        mh_conv_w, mh_conv_b, mh_dt_bias, mh_A_log, mh_D, mh_norm_w,
        mv_conv_w, mv_conv_b, mv_dt_bias, mv_A_log, mv_D, mv_norm_w);

    gemm_mma<<<dim3(NTOK / BMg, D_MODEL / BNg, 1), 256, GSMEM>>>(
        Y, WcBhi, WcBhi, out,
        nullptr, nullptr, nullptr, nullptr, KFIN, D_MODEL, fc_b, 0);
}

// round 16
// speedup vs baseline: 2.7072x; 1.0008x over previous
#include <cuda_runtime.h>
#include <cuda_bf16.h>
#include <cuda_fp16.h>
#include <math.h>
#include <stdint.h>

#define D_MODEL   256
#define D_INNER   512
#define CONV_CH   640
#define SEQ       64
#define NSEQ      512
#define NTOK      32768
#define KFIN      1024
#define NIN       1152

// ---------------- scratch ------------------------------------------------------
__device__ __half g_Z16h[(size_t)NTOK * D_INNER];
__device__ __half g_Z16v[(size_t)NTOK * D_INNER];
__device__ float  g_dth [(size_t)NTOK * 8];
__device__ float  g_dtv [(size_t)NTOK * 8];
__device__ __half g_XBCh[(size_t)NTOK * CONV_CH];
__device__ __half g_XBCv[(size_t)NTOK * CONV_CH];
__device__ __half g_Xhi [(size_t)NTOK * D_MODEL];
__device__ __half g_Whhi[(size_t)NIN * D_MODEL];
__device__ __half g_Wvhi[(size_t)NIN * D_MODEL];
__device__ __half g_Y   [(size_t)NTOK * KFIN];
__device__ __half g_WcBhi[(size_t)D_MODEL * KFIN];

extern __shared__ char dynsm[];

// ---------------- helpers ------------------------------------------------------
__device__ __forceinline__ uint32_t smem_u32(const void* p) {
    uint32_t a;
    asm("{ .reg .u64 t; cvta.to.shared.u64 t, %1; cvt.u32.u64 %0, t; }" : "=r"(a) : "l"(p));
    return a;
}
__device__ __forceinline__ uint32_t swz128(uint32_t off) {
    return off ^ ((off >> 3) & 0x70);
}
#define CP16(dst, src) \
    asm volatile("cp.async.cg.shared.global [%0], [%1], 16;" :: "r"(dst), "l"(src))
#define CP_COMMIT() asm volatile("cp.async.commit_group;" ::: "memory")
#define CP_WAIT(n)  asm volatile("cp.async.wait_group %0;" :: "n"(n) : "memory")

__device__ __forceinline__ void ldm4(uint32_t* r, uint32_t addr) {
    asm volatile("ldmatrix.sync.aligned.m8n8.x4.shared.b16 {%0,%1,%2,%3}, [%4];"
        : "=r"(r[0]), "=r"(r[1]), "=r"(r[2]), "=r"(r[3]) : "r"(addr));
}
__device__ __forceinline__ void mma16816(float* d, const uint32_t* a, uint32_t b0, uint32_t b1) {
    asm volatile("mma.sync.aligned.m16n8k16.row.col.f32.f16.f16.f32 "
        "{%0,%1,%2,%3}, {%4,%5,%6,%7}, {%8,%9}, {%0,%1,%2,%3};"
        : "+f"(d[0]), "+f"(d[1]), "+f"(d[2]), "+f"(d[3])
        : "r"(a[0]), "r"(a[1]), "r"(a[2]), "r"(a[3]), "r"(b0), "r"(b1));
}

// ---------------- prep kernels --------------------------------------------------
__global__ void prep_w_kernel(const float* __restrict__ wh, const float* __restrict__ wv) {
    int i = blockIdx.x * 256 + threadIdx.x;
    if (i < NIN * D_MODEL) {
        g_Whhi[i] = __float2half(wh[i]);
        g_Wvhi[i] = __float2half(wv[i]);
    }
}

// fused: x -> fp16 Xhi  +  exact fp32 dt (both dirs)
__global__ void __launch_bounds__(256) cvtdt_kernel(
    const float* __restrict__ x,
    const float* __restrict__ whd, const float* __restrict__ wvd)
{
    __shared__ float xs[32][260];
    __shared__ float wh[8][260];
    __shared__ float wv[8][260];
    const int tid = threadIdx.x;
    const int row0 = blockIdx.x * 32;
    for (int i = tid; i < 8 * 64; i += 256) {
        int h = i >> 6, c4 = (i & 63) * 4;
        *(float4*)&wh[h][c4] = *(const float4*)&whd[h * 256 + c4];
        *(float4*)&wv[h][c4] = *(const float4*)&wvd[h * 256 + c4];
    }
    for (int i = tid; i < 32 * 64; i += 256) {
        int r = i >> 6, c4 = (i & 63) * 4;
        *(float4*)&xs[r][c4] = *(const float4*)&x[(size_t)(row0 + r) * 256 + c4];
    }
    __syncthreads();
    // fp16 conversion out of smem
    for (int i = tid; i < 32 * 64; i += 256) {
        int r = i >> 6, c4 = (i & 63) * 4;
        float4 v = *(float4*)&xs[r][c4];
        size_t o = ((size_t)(row0 + r) * 256 + c4) >> 1;
        ((__half2*)g_Xhi)[o]     = __floats2half2_rn(v.x, v.y);
        ((__half2*)g_Xhi)[o + 1] = __floats2half2_rn(v.z, v.w);
    }
    const int r = tid >> 3, h = tid & 7;
    float ah = 0.f, av = 0.f;
#pragma unroll 8
    for (int k = 0; k < 256; k += 4) {
        float4 xv = *(float4*)&xs[r][k];
        float4 wa = *(float4*)&wh[h][k];
        float4 wb = *(float4*)&wv[h][k];
        ah = fmaf(xv.x, wa.x, ah); ah = fmaf(xv.y, wa.y, ah);
        ah = fmaf(xv.z, wa.z, ah); ah = fmaf(xv.w, wa.w, ah);
        av = fmaf(xv.x, wb.x, av); av = fmaf(xv.y, wb.y, av);
        av = fmaf(xv.z, wb.z, av); av = fmaf(xv.w, wb.w, av);
    }
    g_dth[(size_t)(row0 + r) * 8 + h] = ah;
    g_dtv[(size_t)(row0 + r) * 8 + h] = av;
}

// ---------------- mma.sync fp16 GEMM, 1-term, BK=64, 3-stage --------------------
// mode==1 (in-proj): fp16 out (Z16 / XBC split)
// mode==0 (final)  : fp32 out + bias
#define BMg 128
#define BNg 128
#define TILE64_B 16384
#define STAGE_B  32768
#define GSMEM    98304

__global__ void __launch_bounds__(256, 2) gemm_mma(
    const __half* __restrict__ A,
    const __half* __restrict__ B0, const __half* __restrict__ B1,
    float* __restrict__ C,
    __half* __restrict__ Z0, __half* __restrict__ X0,
    __half* __restrict__ Z1, __half* __restrict__ X1,
    int K, int ldc, const float* __restrict__ bias, int mode)
{
    const uint32_t smb = smem_u32(dynsm);
    const int tid = threadIdx.x, lane = tid & 31, wid = tid >> 5;
    const int m0 = blockIdx.x * BMg, n0 = blockIdx.y * BNg;
    const int wm = (wid & 1) * 64, wn = 32 * (wid >> 1);
    const int nk = K >> 6;

    const __half* B = blockIdx.z ? B1 : B0;
    __half* Z16 = blockIdx.z ? Z1 : Z0;
    __half* XB  = blockIdx.z ? X1 : X0;

    uint32_t arow[4], brow[2];
#pragma unroll
    for (int mt = 0; mt < 4; mt++)
        arow[mt] = (uint32_t)(wm + mt * 16 + (lane & 15)) * 128 + (lane >> 4) * 16;
#pragma unroll
    for (int nb = 0; nb < 2; nb++)
        brow[nb] = (uint32_t)(wn + nb * 16 + (lane & 15)) * 128 + (lane >> 4) * 16;

    float acc[4][4][4];
#pragma unroll
    for (int a = 0; a < 4; a++)
#pragma unroll
        for (int b = 0; b < 4; b++)
#pragma unroll
            for (int c = 0; c < 4; c++) acc[a][b][c] = 0.f;

    const int lrow = tid >> 1, cq = (tid & 1) * 4;

    auto load_stage = [&](int s, int c) {
        const int koff = c * 64;
        const uint32_t base = smb + s * STAGE_B;
        const __half* pA = A + (size_t)(m0 + lrow) * K + koff;
        const __half* pB = B + (size_t)(n0 + lrow) * K + koff;
        const uint32_t rb = (uint32_t)lrow * 128;
#pragma unroll
        for (int ch = 0; ch < 4; ch++) {
            uint32_t d = swz128(rb + (cq + ch) * 16);
            CP16(base + d, pA + (cq + ch) * 8);
            CP16(base + TILE64_B + d, pB + (cq + ch) * 8);
        }
        CP_COMMIT();
    };

    load_stage(0, 0);
    load_stage(1, 1);

    for (int c = 0; c < nk; c++) {
        if (c + 1 < nk) CP_WAIT(1); else CP_WAIT(0);
        __syncthreads();
        if (c + 2 < nk) load_stage((c + 2) % 3, c + 2);

        const uint32_t base = smb + (c % 3) * STAGE_B;
        const uint32_t aB = base, bB = base + TILE64_B;
#pragma unroll
        for (int ks = 0; ks < 4; ks++) {
            uint32_t af[4][4], bf[2][4];
#pragma unroll
            for (int mt = 0; mt < 4; mt++)
                ldm4(af[mt], aB + swz128(arow[mt] + ks * 32));
#pragma unroll
            for (int nb = 0; nb < 2; nb++)
                ldm4(bf[nb], bB + swz128(brow[nb] + ks * 32));
#pragma unroll
            for (int mt = 0; mt < 4; mt++)
#pragma unroll
                for (int nb = 0; nb < 2; nb++) {
                    mma16816(acc[mt][nb * 2],     af[mt], bf[nb][0], bf[nb][2]);
                    mma16816(acc[mt][nb * 2 + 1], af[mt], bf[nb][1], bf[nb][3]);
                }
        }
    }

#pragma unroll
    for (int mt = 0; mt < 4; mt++) {
        int row = m0 + wm + mt * 16 + (lane >> 2);
#pragma unroll
        for (int nt = 0; nt < 4; nt++) {
            int col = n0 + wn + nt * 8 + (lane & 3) * 2;
            float2 v0 = make_float2(acc[mt][nt][0], acc[mt][nt][1]);
            float2 v1 = make_float2(acc[mt][nt][2], acc[mt][nt][3]);
            if (mode == 1) {
                if (col < 512) {
                    *(__half2*)&Z16[(size_t)row * 512 + col]       = __floats2half2_rn(v0.x, v0.y);
                    *(__half2*)&Z16[(size_t)(row + 8) * 512 + col] = __floats2half2_rn(v1.x, v1.y);
                } else {
                    int xc = col - 512;
                    *(__half2*)&XB[(size_t)row * 640 + xc]       = __floats2half2_rn(v0.x, v0.y);
                    *(__half2*)&XB[(size_t)(row + 8) * 640 + xc] = __floats2half2_rn(v1.x, v1.y);
                }
            } else {
                float b0 = bias[col], b1 = bias[col + 1];
                v0.x += b0; v0.y += b1; v1.x += b0; v1.y += b1;
                *(float2*)&C[(size_t)row * ldc + col] = v0;
                *(float2*)&C[(size_t)(row + 8) * ldc + col] = v1;
            }
        }
    }
}

// ---------------- SSD kernel ----------------------------------------------------
#define RAW_PITCH 1296
#define XDT_PITCH 144
#define G_PITCH   68
#define GSM_PITCH 520

#define GSM_OFF   0
#define G_OFF     66560
#define XDT_OFF   86832
#define BM_OFF    160560
#define CM_OFF    169776
#define GMH_OFF   178992
#define GML_OFF   188208
#define ZBUF_OFF  197424
#define L_OFF     213808
#define DTS_OFF   215856
#define DDT_OFF   217904
#define NW_OFF    219952
#define SSD_SMEM  222000

__global__ void __launch_bounds__(512, 1) ssd_kernel(
    const float* __restrict__ cwh, const float* __restrict__ cbh,
    const float* __restrict__ dtbh, const float* __restrict__ Alh,
    const float* __restrict__ Dh_, const float* __restrict__ nwh,
    const float* __restrict__ cwv, const float* __restrict__ cbv,
    const float* __restrict__ dtbv, const float* __restrict__ Alv,
    const float* __restrict__ Dv_, const float* __restrict__ nwv)
{
    char* sm = dynsm;
    const uint32_t smb = smem_u32(sm);
    const int tid = threadIdx.x, lane = tid & 31, wid = tid >> 5;
    const int dir = blockIdx.x >> 9;
    const int s   = blockIdx.x & 511;

    const __half* Z16     = dir ? g_Z16v : g_Z16h;
    const float*  DT      = dir ? g_dtv : g_dth;
    const __half* XBC     = dir ? g_XBCv : g_XBCh;
    const float*  conv_w  = dir ? cwv : cwh;
    const float*  conv_b  = dir ? cbv : cbh;
    const float*  dt_bias = dir ? dtbv : dtbh;
    const float*  A_log   = dir ? Alv : Alh;
    const float*  Dv      = dir ? Dv_ : Dh_;
    const float*  norm_w  = dir ? nwv : nwh;
    const int ycol = dir ? 0 : 512;

    int base, stride;
    if (dir) { int b = s >> 6, w = s & 63; base = b * 4096 + w; stride = 64; }
    else     { base = s * 64; stride = 1; }

    __half* XdT = (__half*)(sm + XDT_OFF);
    __half* Bm  = (__half*)(sm + BM_OFF);
    __half* Cm  = (__half*)(sm + CM_OFF);
    float*  G   = (float*)(sm + G_OFF);
    float*  Lc  = (float*)(sm + L_OFF);
    float*  dts = (float*)(sm + DTS_OFF);
    float*  Ddt = (float*)(sm + DDT_OFF);
    float*  nws = (float*)(sm + NW_OFF);
    __half* gsm = (__half*)(sm + GSM_OFF);

    nws[tid] = norm_w[tid];
    ((uint32_t*)sm)[tid] = 0;
    if (tid < 460) ((uint32_t*)sm)[tid + 512] = 0;

#pragma unroll
    for (int j = 0; j < 10; j++) {
        int idx = tid + j * 512;
        int row = idx / 80, c16 = idx % 80;
        uint32_t dst = smb + (uint32_t)(row + 3) * RAW_PITCH + c16 * 16;
        const __half* src = XBC + (size_t)(base + row * stride) * 640 + c16 * 8;
        CP16(dst, src);
    }
    CP_COMMIT();

    if (wid < 8) {
        const int h = wid;
        const float Aneg = -__expf(A_log[h]);
        const float dtb = dt_bias[h];
        const float Dh = Dv[h];
        float v0, v1;
        {
            int t = lane;
            float draw = DT[(size_t)(base + t * stride) * 8 + h] + dtb;
            float dt = (draw > 20.f) ? draw : log1pf(__expf(draw));
            dts[h * 64 + t] = dt; Ddt[h * 64 + t] = Dh / dt;
            v0 = dt * Aneg;
        }
        {
            int t = lane + 32;
            float draw = DT[(size_t)(base + t * stride) * 8 + h] + dtb;
            float dt = (draw > 20.f) ? draw : log1pf(__expf(draw));
            dts[h * 64 + t] = dt; Ddt[h * 64 + t] = Dh / dt;
            v1 = dt * Aneg;
        }
        float a = v0;
#pragma unroll
        for (int o = 1; o < 32; o <<= 1) {
            float u = __shfl_up_sync(0xffffffffu, a, o);
            if (lane >= o) a += u;
        }
        float tot = __shfl_sync(0xffffffffu, a, 31);
        float b = v1;
#pragma unroll
        for (int o = 1; o < 32; o <<= 1) {
            float u = __shfl_up_sync(0xffffffffu, b, o);
            if (lane >= o) b += u;
        }
        b += tot;
        Lc[h * 64 + lane] = a;
        Lc[h * 64 + 32 + lane] = b;
    }
    CP_WAIT(0);
    __syncthreads();

    {
        const int c = tid, hd = c >> 6;
        const float w0 = conv_w[c * 4], w1 = conv_w[c * 4 + 1];
        const float w2 = conv_w[c * 4 + 2], w3 = conv_w[c * 4 + 3];
        const float cb = conv_b[c];
        const bool isbc = (tid < 128);
        const int c2 = 512 + tid;
        float u0 = 0, u1 = 0, u2 = 0, u3 = 0, ub = 0;
        __half* dstBC = (tid < 64) ? (Bm + tid) : (Cm + (tid - 64));
        if (isbc) {
            u0 = conv_w[c2 * 4]; u1 = conv_w[c2 * 4 + 1];
            u2 = conv_w[c2 * 4 + 2]; u3 = conv_w[c2 * 4 + 3];
            ub = conv_b[c2];
        }
        float r0 = 0, r1 = 0, r2 = 0, q0 = 0, q1 = 0, q2 = 0;
        for (int t = 0; t < SEQ; t++) {
            float cur = __half2float(*(__half*)(sm + (t + 3) * RAW_PITCH + c * 2));
            float v = fmaf(cur, w3, fmaf(r2, w2, fmaf(r1, w1, fmaf(r0, w0, cb))));
            r0 = r1; r1 = r2; r2 = cur;
            v = v / (1.f + __expf(-v));
            XdT[c * 72 + t] = __float2half(v * dts[hd * 64 + t]);
            if (isbc) {
                float cq = __half2float(*(__half*)(sm + (t + 3) * RAW_PITCH + c2 * 2));
                float vq = fmaf(cq, u3, fmaf(q2, u2, fmaf(q1, u1, fmaf(q0, u0, ub))));
                q0 = q1; q1 = q2; q2 = cq;
                vq = vq / (1.f + __expf(-vq));
                dstBC[t * 72] = __float2half(vq);
            }
        }
    }
    __syncthreads();

    const int mi = wid & 3, nj = wid >> 2;
    {
        float acc[2][4];
#pragma unroll
        for (int i = 0; i < 2; i++)
#pragma unroll
            for (int j = 0; j < 4; j++) acc[i][j] = 0.f;
#pragma unroll
        for (int ks = 0; ks < 4; ks++) {
            uint32_t a[4], bq[4];
            ldm4(a,  smb + CM_OFF + (mi * 16 + (lane & 15)) * XDT_PITCH + (lane >> 4) * 16 + ks * 32);
            ldm4(bq, smb + BM_OFF + (nj * 16 + (lane & 15)) * XDT_PITCH + (lane >> 4) * 16 + ks * 32);
            mma16816(acc[0], a, bq[0], bq[2]);
            mma16816(acc[1], a, bq[1], bq[3]);
        }
        const int r = lane >> 2, cc = (lane & 3) * 2;
#pragma unroll
        for (int nt = 0; nt < 2; nt++) {
            int sc = nj * 16 + nt * 8 + cc;
            *(float2*)&G[(mi * 16 + r) * G_PITCH + sc]     = make_float2(acc[nt][0], acc[nt][1]);
            *(float2*)&G[(mi * 16 + r + 8) * G_PITCH + sc] = make_float2(acc[nt][2], acc[nt][3]);
        }
    }

    auto prefetch_z = [&](int h, int buf) {
        int t = tid >> 3, c16 = tid & 7;
        uint32_t dst = smb + ZBUF_OFF + buf * 8192 + t * 128 + c16 * 16;
        const __half* src = Z16 + (size_t)(base + t * stride) * 512 + h * 64 + c16 * 8;
        CP16(dst, src);
        CP_COMMIT();
    };
    prefetch_z(0, 0);
    __syncthreads();

    for (int h = 0; h < 8; h++) {
        if (h < 7) { prefetch_z(h + 1, (h + 1) & 1); CP_WAIT(1); }
        else       { CP_WAIT(0); }

        const float* Lh = Lc + h * 64;
        __half* Gmh = (__half*)(sm + GMH_OFF);
        __half* Gml = (__half*)(sm + GML_OFF);
#pragma unroll
        for (int k = 0; k < 8; k++) {
            int idx = tid + k * 512;
            int t = idx >> 6, sc = idx & 63;
            float w = 0.f;
            if (sc <= t) w = __expf(Lh[t] - Lh[sc]);
            float gm = G[t * G_PITCH + sc] * w;
            if (sc == t) gm += Ddt[h * 64 + t];
            __half hi = __float2half(gm);
            Gmh[t * 72 + sc] = hi;
            Gml[t * 72 + sc] = __float2half(gm - __half2float(hi));
        }
        __syncthreads();

        float acc[2][4];
#pragma unroll
        for (int i = 0; i < 2; i++)
#pragma unroll
            for (int j = 0; j < 4; j++) acc[i][j] = 0.f;
#pragma unroll
        for (int ks = 0; ks < 4; ks++) {
            uint32_t ah[4], al[4], bq[4];
            uint32_t ro = (mi * 16 + (lane & 15)) * XDT_PITCH + (lane >> 4) * 16 + ks * 32;
            ldm4(ah, smb + GMH_OFF + ro);
            ldm4(al, smb + GML_OFF + ro);
            ldm4(bq, smb + XDT_OFF + (uint32_t)(h * 64 + nj * 16 + (lane & 15)) * XDT_PITCH
                        + (lane >> 4) * 16 + ks * 32);
            mma16816(acc[0], ah, bq[0], bq[2]);
            mma16816(acc[1], ah, bq[1], bq[3]);
            mma16816(acc[0], al, bq[0], bq[2]);
            mma16816(acc[1], al, bq[1], bq[3]);
        }
        const int r = lane >> 2, cc = (lane & 3) * 2;
        const char* zbase = sm + ZBUF_OFF + (h & 1) * 8192;
#pragma unroll
        for (int nt = 0; nt < 2; nt++)
#pragma unroll
            for (int rr = 0; rr < 2; rr++) {
                int t = mi * 16 + r + rr * 8;
                int p = nj * 16 + nt * 8 + cc;
                float y0 = acc[nt][rr * 2 + 0], y1 = acc[nt][rr * 2 + 1];
                __half2 zv = *(__half2*)(zbase + t * 128 + p * 2);
                float z0 = __half2float(zv.x), z1 = __half2float(zv.y);
                float g0 = y0 * z0 / (1.f + __expf(-z0));
                float g1 = y1 * z1 / (1.f + __expf(-z1));
                *(__half2*)&gsm[t * GSM_PITCH + h * 64 + p] = __floats2half2_rn(g0, g1);
            }
        __syncthreads();
    }

#pragma unroll
    for (int k = 0; k < 4; k++) {
        int t = wid + k * 16;
        float ss = 0.f;
        float2 gv[8];
#pragma unroll
        for (int j = 0; j < 8; j++) {
            __half2 hv = *(__half2*)&gsm[t * GSM_PITCH + j * 64 + lane * 2];
            float a = __half2float(hv.x), b = __half2float(hv.y);
            gv[j] = make_float2(a, b);
            ss = fmaf(a, a, ss); ss = fmaf(b, b, ss);
        }
#pragma unroll
        for (int o = 16; o; o >>= 1) ss += __shfl_xor_sync(0xffffffffu, ss, o);
        float sinv = rsqrtf(ss * (1.0f / 512.0f) + 1e-5f);
        size_t orow = (size_t)(base + t * stride) * KFIN + ycol;
#pragma unroll
        for (int j = 0; j < 8; j++) {
            int c = j * 64 + lane * 2;
            float a = gv[j].x * sinv * nws[c];
            float b = gv[j].y * sinv * nws[c + 1];
            *(__half2*)&g_Y[orow + c] = __floats2half2_rn(a, b);
        }
    }
}

// ---------------- fold fc_w into out_w (fp16 out, 256 blocks) -------------------
__global__ void __launch_bounds__(256) wcomb_kernel(
    const float* __restrict__ mh_out_w, const float* __restrict__ mv_out_w,
    const float* __restrict__ fc_w)
{
    const int d  = blockIdx.x;
    const int k0 = blockIdx.y * 32;
    const int nb = blockIdx.z * 32;
    const float* ow = d ? mh_out_w : mv_out_w;
    const int fo = d ? 512 : 0;
    __shared__ float ows[64][33];
    __shared__ float fs[32][65];
    const int kk = threadIdx.x & 31;
    const int ng = threadIdx.x >> 5;       // 0..7, 4 n each
    float acc[4];
#pragma unroll
    for (int i = 0; i < 4; i++) acc[i] = 0.f;

    for (int jo = 0; jo < 256; jo += 64) {
        for (int idx = threadIdx.x; idx < 64 * 32; idx += 256) {
            int j = idx >> 5, k = idx & 31;
            ows[j][k] = ow[(size_t)(jo + j) * 512 + k0 + k];
        }
        for (int idx = threadIdx.x; idx < 32 * 64; idx += 256) {
            int n = idx >> 6, jj = idx & 63;
            fs[n][jj] = fc_w[(size_t)(nb + n) * 1024 + fo + jo + jj] +
                        fc_w[(size_t)(nb + n) * 1024 + fo + 256 + jo + jj];
        }
        __syncthreads();
#pragma unroll 4
        for (int j = 0; j < 64; j++) {
            float o = ows[j][kk];
#pragma unroll
            for (int i = 0; i < 4; i++)
                acc[i] = fmaf(o, fs[ng * 4 + i][j], acc[i]);
        }
        __syncthreads();
    }
#pragma unroll
    for (int i = 0; i < 4; i++)
        g_WcBhi[(size_t)(nb + ng * 4 + i) * KFIN + d * 512 + (k0 + kk)] = __float2half(acc[i]);
}

// ---------------- launch ----------------
extern "C" void kernel_launch(void* const* d_in, const int* in_sizes, int n_in,
                              void* d_out, int out_size)
{
    (void)in_sizes; (void)n_in; (void)out_size;
    const float* x          = (const float*)d_in[0];
    const float* mh_in_w    = (const float*)d_in[1];
    const float* mh_conv_w  = (const float*)d_in[2];
    const float* mh_conv_b  = (const float*)d_in[3];
    const float* mh_dt_bias = (const float*)d_in[4];
    const float* mh_A_log   = (const float*)d_in[5];
    const float* mh_D       = (const float*)d_in[6];
    const float* mh_norm_w  = (const float*)d_in[7];
    const float* mh_out_w   = (const float*)d_in[8];
    const float* mv_in_w    = (const float*)d_in[9];
    const float* mv_conv_w  = (const float*)d_in[10];
    const float* mv_conv_b  = (const float*)d_in[11];
    const float* mv_dt_bias = (const float*)d_in[12];
    const float* mv_A_log   = (const float*)d_in[13];
    const float* mv_D       = (const float*)d_in[14];
    const float* mv_norm_w  = (const float*)d_in[15];
    const float* mv_out_w   = (const float*)d_in[16];
    const float* fc_w       = (const float*)d_in[17];
    const float* fc_b       = (const float*)d_in[18];
    float* out = (float*)d_out;

    __half *Z16h, *Z16v, *XBCh, *XBCv, *Xhi, *Whhi, *Wvhi, *Y, *WcBhi;
    cudaGetSymbolAddress((void**)&Z16h, g_Z16h);
    cudaGetSymbolAddress((void**)&Z16v, g_Z16v);
    cudaGetSymbolAddress((void**)&XBCh, g_XBCh);
    cudaGetSymbolAddress((void**)&XBCv, g_XBCv);
    cudaGetSymbolAddress((void**)&Xhi,  g_Xhi);
    cudaGetSymbolAddress((void**)&Whhi, g_Whhi);
    cudaGetSymbolAddress((void**)&Wvhi, g_Wvhi);
    cudaGetSymbolAddress((void**)&Y,    g_Y);
    cudaGetSymbolAddress((void**)&WcBhi, g_WcBhi);

    cudaFuncSetAttribute(gemm_mma, cudaFuncAttributeMaxDynamicSharedMemorySize, GSMEM);
    cudaFuncSetAttribute(ssd_kernel, cudaFuncAttributeMaxDynamicSharedMemorySize, SSD_SMEM);

    prep_w_kernel<<<(NIN * D_MODEL + 255) / 256, 256>>>(mh_in_w, mv_in_w);
    wcomb_kernel<<<dim3(2, 16, 8), 256>>>(mh_out_w, mv_out_w, fc_w);
    cvtdt_kernel<<<NTOK / 32, 256>>>(x, mh_in_w + 1152 * 256, mv_in_w + 1152 * 256);

    gemm_mma<<<dim3(NTOK / BMg, NIN / BNg, 2), 256, GSMEM>>>(
        Xhi, Whhi, Wvhi, nullptr,
        Z16h, XBCh, Z16v, XBCv, D_MODEL, 0, nullptr, 1);

    ssd_kernel<<<2 * NSEQ, 512, SSD_SMEM>>>(
        mh_conv_w, mh_conv_b, mh_dt_bias, mh_A_log, mh_D, mh_norm_w,
        mv_conv_w, mv_conv_b, mv_dt_bias, mv_A_log, mv_D, mv_norm_w);

    gemm_mma<<<dim3(NTOK / BMg, D_MODEL / BNg, 1), 256, GSMEM>>>(
        Y, WcBhi, WcBhi, out,
        nullptr, nullptr, nullptr, nullptr, KFIN, D_MODEL, fc_b, 0);
}